// round 12
// baseline (speedup 1.0000x reference)
#include <cuda_runtime.h>
#include <cstdint>

// ---------------------------------------------------------------------------
// BinaryConnectNet forward (compute_103-safe: mma.sync/ldmatrix/cp.async).
//  conv1: dw3x3(g=3)+pw1x1(3->128), sign, maxpool2   -> a1 [1024][256pix][128c] int8
//  conv2: dw3x3(g=128)+pw1x1(128->256), sign, pool2  -> a2 [1024][16384] int8 (+-1)
//  fc1:   W quantized to 2 balanced base-128 int8 digits (scale 2^-18);
//         IMMA GEMM [1024 x 2048 x 16384] -> exact s32 planes -> recombine.
//         Per-row residual bound R_j = sum|w - recon|: any |preact| > R_j has
//         provably correct sign; pairs inside the band (~1%) are recomputed
//         exactly in fp64 via an atomic worklist.  sign -> a3 int8.
//  fc2:   a3 @ W2^T + b2 -> out [1024][10] fp32
// ---------------------------------------------------------------------------

__device__ int8_t g_a1[1024 * 256 * 128];
__device__ int8_t g_a2[1024 * 16384];
__device__ int8_t g_a3[1024 * 1024];
__device__ int8_t g_w1d[2ull * 1024 * 16384];   // [p][j][k] digit planes
__device__ int    g_s32[2ull * 1024 * 1024];    // [p][m][j] s32 partials
__device__ float  g_R[1024];                    // per-j residual bound
__device__ int    g_cnt;                        // worklist count
__device__ int    g_list[1024 * 1024];          // worklist (m*1024+j)

__device__ __forceinline__ float fsign(float v) {
    return (v > 0.f) ? 1.f : ((v < 0.f) ? -1.f : 0.f);
}
__device__ __forceinline__ int isign(int v) { return (v > 0) - (v < 0); }

__device__ __forceinline__ uint32_t smem_u32(const void* p) {
    uint32_t a;
    asm("{ .reg .u64 t; cvta.to.shared.u64 t, %1; cvt.u32.u64 %0, t; }"
        : "=r"(a) : "l"(p));
    return a;
}
__device__ __forceinline__ void cp16(uint32_t dst, const void* src) {
    asm volatile("cp.async.cg.shared.global [%0], [%1], 16;"
                 :: "r"(dst), "l"(src) : "memory");
}
__device__ __forceinline__ void ldsm4(uint32_t* r, uint32_t addr) {
    asm volatile("ldmatrix.sync.aligned.m8n8.x4.shared.b16 {%0,%1,%2,%3}, [%4];"
                 : "=r"(r[0]), "=r"(r[1]), "=r"(r[2]), "=r"(r[3]) : "r"(addr));
}
__device__ __forceinline__ void imma(int* c, const uint32_t* a,
                                     uint32_t b0, uint32_t b1) {
    asm volatile("mma.sync.aligned.m16n8k32.row.col.s32.s8.s8.s32 "
                 "{%0,%1,%2,%3}, {%4,%5,%6,%7}, {%8,%9}, {%0,%1,%2,%3};"
                 : "+r"(c[0]), "+r"(c[1]), "+r"(c[2]), "+r"(c[3])
                 : "r"(a[0]), "r"(a[1]), "r"(a[2]), "r"(a[3]),
                   "r"(b0), "r"(b1));
}

// ---------------------------------------------------------------------------
// Kernel 0: zero the worklist counter.
// ---------------------------------------------------------------------------
__global__ void k_zero() { g_cnt = 0; }

// ---------------------------------------------------------------------------
// Kernel 1: conv1 dw + pw + sign + maxpool, one image per block.
// ---------------------------------------------------------------------------
__global__ __launch_bounds__(256) void k_conv1(
    const float* __restrict__ x,
    const float* __restrict__ w1dw, const float* __restrict__ b1dw,
    const float* __restrict__ w1pw, const float* __restrict__ b1pw)
{
    __shared__ float sx[3][32][32];
    __shared__ float sdw[3][32][32];
    __shared__ float swdw[27];
    __shared__ float sbdw[3];
    __shared__ float swpw[128 * 3];
    __shared__ float sbpw[128];

    const int n = blockIdx.x, tid = threadIdx.x;

    for (int i = tid; i < 3072; i += 256) ((float*)sx)[i] = x[n * 3072 + i];
    if (tid < 27)  swdw[tid] = fsign(w1dw[tid]);
    if (tid < 3)   sbdw[tid] = fsign(b1dw[tid]);
    for (int i = tid; i < 384; i += 256) swpw[i] = fsign(w1pw[i]);
    if (tid < 128) sbpw[tid] = fsign(b1pw[tid]);
    __syncthreads();

    for (int i = tid; i < 3072; i += 256) {
        int c = i >> 10, p = i & 1023, y = p >> 5, xx = p & 31;
        float acc = 0.f;
#pragma unroll
        for (int ky = 0; ky < 3; ky++) {
#pragma unroll
            for (int kx = 0; kx < 3; kx++) {
                int yy = y + ky - 1, xw = xx + kx - 1;
                if (yy >= 0 && yy < 32 && xw >= 0 && xw < 32)
                    acc += swdw[c * 9 + ky * 3 + kx] * sx[c][yy][xw];
            }
        }
        acc += sbdw[c];
        ((float*)sdw)[i] = acc;
    }
    __syncthreads();

    for (int i = tid; i < 32768; i += 256) {
        int oc = i & 127, pp = i >> 7;
        int oy = pp >> 4, ox = pp & 15;
        float w0 = swpw[oc * 3 + 0], w1 = swpw[oc * 3 + 1],
              w2 = swpw[oc * 3 + 2], bb = sbpw[oc];
        float vmax = -1e30f;
#pragma unroll
        for (int d = 0; d < 4; d++) {
            int y = 2 * oy + (d >> 1), xw = 2 * ox + (d & 1);
            float v = w0 * sdw[0][y][xw] + w1 * sdw[1][y][xw]
                    + w2 * sdw[2][y][xw] + bb;
            vmax = fmaxf(vmax, v);
        }
        g_a1[n * 32768 + pp * 128 + oc] = (int8_t)(int)fsign(vmax);
    }
}

// ---------------------------------------------------------------------------
// Kernel 2: conv2 dw (int) + pw (dp4a) + sign + maxpool, one image per block.
// ---------------------------------------------------------------------------
__global__ __launch_bounds__(256) void k_conv2(
    const float* __restrict__ w2dw, const float* __restrict__ b2dw,
    const float* __restrict__ w2pw, const float* __restrict__ b2pw)
{
    extern __shared__ char sm[];
    int8_t* s_a1 = (int8_t*)sm;
    int8_t* s_t  = (int8_t*)(sm + 32768);
    int8_t* s_w  = (int8_t*)(sm + 65536);
    int8_t* s_wd = (int8_t*)(sm + 98304);
    int8_t* s_bd = (int8_t*)(sm + 99456);
    int8_t* s_bp = (int8_t*)(sm + 99584);

    const int n = blockIdx.x, tid = threadIdx.x;

    {
        const uint4* src = (const uint4*)(g_a1 + n * 32768);
        uint4* dst = (uint4*)s_a1;
        for (int i = tid; i < 2048; i += 256) dst[i] = src[i];
    }
    for (int i = tid; i < 1152; i += 256) s_wd[i] = (int8_t)(int)fsign(w2dw[i]);
    for (int i = tid; i < 32768; i += 256) s_w[i] = (int8_t)(int)fsign(w2pw[i]);
    if (tid < 128) s_bd[tid] = (int8_t)(int)fsign(b2dw[tid]);
    s_bp[tid] = (int8_t)(int)fsign(b2pw[tid]);
    __syncthreads();

    for (int i = tid; i < 32768; i += 256) {
        int c = i & 127, p = i >> 7, y = p >> 4, xx = p & 15;
        int acc = (int)s_bd[c];
#pragma unroll
        for (int ky = 0; ky < 3; ky++) {
#pragma unroll
            for (int kx = 0; kx < 3; kx++) {
                int yy = y + ky - 1, xw = xx + kx - 1;
                if (yy >= 0 && yy < 16 && xw >= 0 && xw < 16)
                    acc += (int)s_wd[c * 9 + ky * 3 + kx]
                         * (int)s_a1[(yy * 16 + xw) * 128 + c];
            }
        }
        s_t[p * 128 + c] = (int8_t)acc;
    }
    __syncthreads();

    {
        const int oc = tid;
        uint32_t wreg[32];
        const uint32_t* wsrc = (const uint32_t*)s_w + oc * 32;
#pragma unroll
        for (int j = 0; j < 32; j++) wreg[j] = wsrc[j];
        const int bb = (int)s_bp[oc];
        int8_t* s_a2 = s_a1;
        const uint4* t4 = (const uint4*)s_t;

        for (int q = 0; q < 64; q++) {
            int py = q >> 3, px = q & 7;
            int vmax = -2000000000;
#pragma unroll
            for (int d = 0; d < 4; d++) {
                int p = (2 * py + (d >> 1)) * 16 + 2 * px + (d & 1);
                int acc = bb;
#pragma unroll
                for (int jj = 0; jj < 8; jj++) {
                    uint4 t = t4[p * 8 + jj];
                    acc = __dp4a((int)t.x, (int)wreg[jj * 4 + 0], acc);
                    acc = __dp4a((int)t.y, (int)wreg[jj * 4 + 1], acc);
                    acc = __dp4a((int)t.z, (int)wreg[jj * 4 + 2], acc);
                    acc = __dp4a((int)t.w, (int)wreg[jj * 4 + 3], acc);
                }
                vmax = max(vmax, acc);
            }
            s_a2[oc * 64 + q] = (int8_t)isign(vmax);
        }
    }
    __syncthreads();

    {
        uint4* g = (uint4*)(g_a2 + n * 16384);
        const uint4* s2 = (const uint4*)s_a1;
        for (int i = tid; i < 1024; i += 256) g[i] = s2[i];
    }
}

// ---------------------------------------------------------------------------
// Kernel W: per-j (one block per output row j):
//   n = round(w * 2^18); d0 = balanced high digit, d1 = low digit (clamped
//   defensively); write 2 int8 planes; accumulate R_j = sum |w - recon*2^-18|.
// ---------------------------------------------------------------------------
__global__ __launch_bounds__(256) void k_wsplit(const float* __restrict__ W)
{
    __shared__ double rs[256];
    const int j = blockIdx.x, tid = threadIdx.x;
    const float4* W4 = (const float4*)(W + (size_t)j * 16384);
    char4* P0 = (char4*)(g_w1d + (size_t)j * 16384);
    char4* P1 = (char4*)(g_w1d + (1ull << 24) + (size_t)j * 16384);

    double part = 0.0;
    const double inv = 1.0 / 262144.0;
#pragma unroll 4
    for (int it = 0; it < 16; it++) {
        const int k4 = tid + (it << 8);
        float4 w = W4[k4];
        float wv[4] = {w.x, w.y, w.z, w.w};
        char dd0[4], dd1[4];
#pragma unroll
        for (int c = 0; c < 4; c++) {
            int n = __float2int_rn(wv[c] * 262144.0f);   // exact: pow2 scale
            int d0 = (n + 64) >> 7;
            d0 = max(-127, min(127, d0));
            int d1 = n - (d0 << 7);
            d1 = max(-127, min(127, d1));
            int recon = (d0 << 7) + d1;
            part += fabs((double)wv[c] - (double)recon * inv);
            dd0[c] = (char)d0; dd1[c] = (char)d1;
        }
        P0[k4] = make_char4(dd0[0], dd0[1], dd0[2], dd0[3]);
        P1[k4] = make_char4(dd1[0], dd1[1], dd1[2], dd1[3]);
    }
    rs[tid] = part;
    __syncthreads();
    for (int s = 128; s; s >>= 1) {
        if (tid < s) rs[tid] += rs[tid + s];
        __syncthreads();
    }
    if (tid == 0) g_R[j] = (float)(rs[0] * 1.000001 + 1e-12);
}

// ---------------------------------------------------------------------------
// Kernel 3: fc1 IMMA GEMM  S[1024m][2048n'] = a2 @ Wdigits^T (s8 -> s32).
// CTA: 128m x 128n, BK=128, 4-stage cp.async (128KB), 8 warps of 64m x 32n.
// Grid (16, 8) = 128 CTAs.
// ---------------------------------------------------------------------------
static constexpr int ST_A  = 16384;     // 128 rows * 128B
static constexpr int ST_SZ = 32768;     // + 128 rows * 128B for B

__device__ __forceinline__ void gemm_load_stage(
    uint32_t stage, const int8_t* Ag, const int8_t* Bg, int kt, int tid)
{
    const int k0 = kt << 7;
#pragma unroll
    for (int r = 0; r < 4; r++) {           // A: 1024 16B chunks
        int c = tid + (r << 8);
        int row = c >> 3, seg = (c & 7) << 4;
        uint32_t dst = stage + row * 128 + (seg ^ ((row & 7) << 4));
        cp16(dst, Ag + (size_t)row * 16384 + k0 + seg);
    }
#pragma unroll
    for (int r = 0; r < 4; r++) {           // B: 1024 16B chunks
        int c = tid + (r << 8);
        int row = c >> 3, seg = (c & 7) << 4;
        uint32_t dst = stage + ST_A + row * 128 + (seg ^ ((row & 7) << 4));
        cp16(dst, Bg + (size_t)row * 16384 + k0 + seg);
    }
}

__global__ __launch_bounds__(256, 1) void k_fc1imma()
{
    extern __shared__ char sm[];
    const uint32_t smb = smem_u32(sm);

    const int tid = threadIdx.x, wid = tid >> 5, l = tid & 31;
    const int n0 = blockIdx.x * 128, m0 = blockIdx.y * 128;
    const int warp_m = wid & 1, warp_n = wid >> 1;

    const int8_t* Ag = g_a2 + (size_t)m0 * 16384;
    const int8_t* Bg = g_w1d + (size_t)n0 * 16384;

    const int rowA = l & 15;
    const uint32_t cA = (uint32_t)(((l >> 4) << 4) ^ ((l & 7) << 4));
    const int rowB = (l & 7) + ((l >> 4) << 3);
    const uint32_t cB = (uint32_t)((((l >> 3) & 1) << 4) ^ ((l & 7) << 4));
    const uint32_t aBase = (uint32_t)((warp_m * 64 + rowA) * 128);
    const uint32_t bBase = (uint32_t)(ST_A + (warp_n * 32 + rowB) * 128);

    int c[4][4][4];
#pragma unroll
    for (int i = 0; i < 4; i++)
#pragma unroll
        for (int nn = 0; nn < 4; nn++)
#pragma unroll
            for (int q = 0; q < 4; q++) c[i][nn][q] = 0;

    gemm_load_stage(smb + 0 * ST_SZ, Ag, Bg, 0, tid);
    asm volatile("cp.async.commit_group;" ::: "memory");
    gemm_load_stage(smb + 1 * ST_SZ, Ag, Bg, 1, tid);
    asm volatile("cp.async.commit_group;" ::: "memory");
    gemm_load_stage(smb + 2 * ST_SZ, Ag, Bg, 2, tid);
    asm volatile("cp.async.commit_group;" ::: "memory");

    for (int it = 0; it < 128; it++) {
        asm volatile("cp.async.wait_group 2;" ::: "memory");
        __syncthreads();
        if (it + 3 < 128)
            gemm_load_stage(smb + ((it + 3) & 3) * ST_SZ, Ag, Bg, it + 3, tid);
        asm volatile("cp.async.commit_group;" ::: "memory");

        const uint32_t buf = smb + (it & 3) * ST_SZ;
#pragma unroll
        for (int kk = 0; kk < 4; kk++) {
            const uint32_t ka = ((uint32_t)(kk << 5)) ^ cA;
            const uint32_t kb = ((uint32_t)(kk << 5)) ^ cB;
            uint32_t a[4][4], b[2][4];
#pragma unroll
            for (int i = 0; i < 4; i++)
                ldsm4(a[i], buf + aBase + i * 2048 + ka);
#pragma unroll
            for (int t = 0; t < 2; t++)
                ldsm4(b[t], buf + bBase + t * 2048 + kb);
#pragma unroll
            for (int i = 0; i < 4; i++)
#pragma unroll
                for (int t = 0; t < 2; t++) {
                    imma(c[i][2 * t],     a[i], b[t][0], b[t][1]);
                    imma(c[i][2 * t + 1], a[i], b[t][2], b[t][3]);
                }
        }
    }
    __syncthreads();

    // epilogue: frags -> smem [128][132] -> coalesced global
    int* so = (int*)sm;
    const int gm = l >> 2, gn = (l & 3) << 1;
#pragma unroll
    for (int i = 0; i < 4; i++) {
        int ml = warp_m * 64 + i * 16 + gm;
#pragma unroll
        for (int nn = 0; nn < 4; nn++) {
            int nl = warp_n * 32 + nn * 8 + gn;
            so[ml * 132 + nl]           = c[i][nn][0];
            so[ml * 132 + nl + 1]       = c[i][nn][1];
            so[(ml + 8) * 132 + nl]     = c[i][nn][2];
            so[(ml + 8) * 132 + nl + 1] = c[i][nn][3];
        }
    }
    __syncthreads();
    {
        const int plane = n0 >> 10, jb = n0 & 1023;
        int* gp = g_s32 + ((size_t)plane << 20) + (size_t)m0 * 1024 + jb;
        for (int i = tid; i < 16384; i += 256) {
            int ml = i >> 7, nl = i & 127;
            gp[(size_t)ml * 1024 + nl] = so[ml * 132 + nl];
        }
    }
}

// ---------------------------------------------------------------------------
// Kernel 3b: recombine planes + bias; sign when |v| > R_j (provably correct);
// otherwise push (m,j) onto the worklist.  One block per m.
// ---------------------------------------------------------------------------
__global__ __launch_bounds__(256) void k_recflag(const float* __restrict__ bf)
{
    __shared__ int s_cnt, s_base;
    __shared__ int s_list[1024];

    const int m = blockIdx.x, t = threadIdx.x;
    if (t == 0) s_cnt = 0;
    __syncthreads();

    const int4 s0 = ((const int4*)(g_s32 + (size_t)m * 1024))[t];
    const int4 s1 = ((const int4*)(g_s32 + (1ull << 20) + (size_t)m * 1024))[t];
    const float4 bb = ((const float4*)bf)[t];
    const float4 Rr = ((const float4*)g_R)[t];

    const double inv = 1.0 / 262144.0;
    int sv[4] = {s0.x, s0.y, s0.z, s0.w};
    int lv[4] = {s1.x, s1.y, s1.z, s1.w};
    float bv[4] = {bb.x, bb.y, bb.z, bb.w};
    float Rv[4] = {Rr.x, Rr.y, Rr.z, Rr.w};

    char o[4];
#pragma unroll
    for (int cix = 0; cix < 4; cix++) {
        long long S = ((long long)sv[cix] << 7) + lv[cix];
        double v = (double)S * inv + (double)bv[cix];
        o[cix] = (char)((v > 0.0) ? 1 : ((v < 0.0) ? -1 : 0));
        if (fabs(v) <= (double)Rv[cix]) {
            int p = atomicAdd(&s_cnt, 1);
            s_list[p] = m * 1024 + t * 4 + cix;
        }
    }
    ((char4*)g_a3)[m * 256 + t] = make_char4(o[0], o[1], o[2], o[3]);
    __syncthreads();

    if (t == 0 && s_cnt > 0) s_base = atomicAdd(&g_cnt, s_cnt);
    __syncthreads();
    for (int i = t; i < s_cnt; i += 256) g_list[s_base + i] = s_list[i];
}

// ---------------------------------------------------------------------------
// Kernel 3c: fp64 exact recompute of flagged pairs; overwrite a3 sign.
// ---------------------------------------------------------------------------
__global__ __launch_bounds__(256) void k_fixup(
    const float* __restrict__ W, const float* __restrict__ bf)
{
    __shared__ double rs[256];
    const int t = threadIdx.x;
    const int cnt = g_cnt;

    for (int e = blockIdx.x; e < cnt; e += gridDim.x) {
        const int pair = g_list[e];
        const int m = pair >> 10, j = pair & 1023;
        const float* wr = W + (size_t)j * 16384;
        const int8_t* ar = g_a2 + (size_t)m * 16384;

        double acc0 = 0.0, acc1 = 0.0;
        for (int k = t; k < 16384; k += 512) {
            acc0 += (double)wr[k] * (double)ar[k];
            acc1 += (double)wr[k + 256] * (double)ar[k + 256];
        }
        rs[t] = acc0 + acc1;
        __syncthreads();
        for (int s = 128; s; s >>= 1) {
            if (t < s) rs[t] += rs[t + s];
            __syncthreads();
        }
        if (t == 0) {
            double v = rs[0] + (double)bf[j];
            g_a3[(size_t)m * 1024 + j] =
                (char)((v > 0.0) ? 1 : ((v < 0.0) ? -1 : 0));
        }
        __syncthreads();
    }
}

// ---------------------------------------------------------------------------
// Kernel 4: fc2  out[1024][10] = a3 @ W2^T + b2
// ---------------------------------------------------------------------------
__global__ __launch_bounds__(128) void k_fc2(
    const float* __restrict__ W2, const float* __restrict__ b2,
    float* __restrict__ out)
{
    const int n = blockIdx.x, tid = threadIdx.x;
    float acc[10] = {};
    const int8_t* a = g_a3 + n * 1024;
    for (int k = tid; k < 1024; k += 128) {
        float s = (float)a[k];
#pragma unroll
        for (int j = 0; j < 10; j++) acc[j] += s * W2[j * 1024 + k];
    }
#pragma unroll
    for (int j = 0; j < 10; j++)
#pragma unroll
        for (int off = 16; off; off >>= 1)
            acc[j] += __shfl_down_sync(0xffffffffu, acc[j], off);

    __shared__ float red[4][10];
    int w = tid >> 5, lm = tid & 31;
    if (lm == 0)
#pragma unroll
        for (int j = 0; j < 10; j++) red[w][j] = acc[j];
    __syncthreads();
    if (tid < 10) {
        float v = red[0][tid] + red[1][tid] + red[2][tid] + red[3][tid] + b2[tid];
        out[n * 10 + tid] = v;
    }
}

// ---------------------------------------------------------------------------
extern "C" void kernel_launch(void* const* d_in, const int* in_sizes, int n_in,
                              void* d_out, int out_size)
{
    const float* x    = (const float*)d_in[0];
    const float* w1dw = (const float*)d_in[1];
    const float* b1dw = (const float*)d_in[2];
    const float* w1pw = (const float*)d_in[3];
    const float* b1pw = (const float*)d_in[4];
    const float* w2dw = (const float*)d_in[5];
    const float* b2dw = (const float*)d_in[6];
    const float* w2pw = (const float*)d_in[7];
    const float* b2pw = (const float*)d_in[8];
    const float* fc1w = (const float*)d_in[9];
    const float* fc1b = (const float*)d_in[10];
    const float* fc2w = (const float*)d_in[11];
    const float* fc2b = (const float*)d_in[12];
    float* out = (float*)d_out;

    const int SMEM2 = 99840;
    cudaFuncSetAttribute(k_conv2, cudaFuncAttributeMaxDynamicSharedMemorySize, SMEM2);
    const int SMEMG = 4 * ST_SZ;   // 131072
    cudaFuncSetAttribute(k_fc1imma, cudaFuncAttributeMaxDynamicSharedMemorySize, SMEMG);

    k_zero<<<1, 1>>>();
    k_wsplit<<<1024, 256>>>(fc1w);
    k_conv1<<<1024, 256>>>(x, w1dw, b1dw, w1pw, b1pw);
    k_conv2<<<1024, 256, SMEM2>>>(w2dw, b2dw, w2pw, b2pw);
    k_fc1imma<<<dim3(16, 8), 256, SMEMG>>>();
    k_recflag<<<1024, 256>>>(fc1b);
    k_fixup<<<256, 256>>>(fc1w, fc1b);
    k_fc2<<<1024, 128>>>(fc2w, fc2b, out);
}

// round 13
// speedup vs baseline: 1.0988x; 1.0988x over previous
#include <cuda_runtime.h>
#include <cstdint>

// ---------------------------------------------------------------------------
// BinaryConnectNet forward (compute_103-safe: mma.sync/ldmatrix/cp.async).
//  conv1: dw3x3(g=3)+pw1x1(3->128), sign, maxpool2   -> a1 [1024][256pix][128c] int8
//  conv2: dw3x3(g=128) via dp4a + pw1x1 dp4a + sign + pool -> a2 int8 (+-1)
//  fc1:   W -> 2 balanced base-128 int8 digits (scale 2^-18); split-K IMMA
//         GEMM (R10-proven tile shape) -> exact s32; recombine + residual
//         bound R_j; pairs inside band recomputed exactly in fp64. sign->a3.
//  fc2:   a3 @ W2^T + b2 -> out [1024][10] fp32
// ---------------------------------------------------------------------------

__device__ int8_t g_a1[1024 * 256 * 128];
__device__ int8_t g_a2[1024 * 16384];
__device__ int8_t g_a3[1024 * 1024];
__device__ int8_t g_w1d[2ull * 1024 * 16384];   // [plane][j][k] digit planes
__device__ int    g_s32k[2ull * 1024 * 2048];   // [kslice][m][n'] partials
__device__ float  g_R[1024];                    // per-j residual bound
__device__ int    g_cnt;
__device__ int    g_list[1024 * 1024];

__device__ __forceinline__ float fsign(float v) {
    return (v > 0.f) ? 1.f : ((v < 0.f) ? -1.f : 0.f);
}
__device__ __forceinline__ int isign(int v) { return (v > 0) - (v < 0); }

__device__ __forceinline__ uint32_t smem_u32(const void* p) {
    uint32_t a;
    asm("{ .reg .u64 t; cvta.to.shared.u64 t, %1; cvt.u32.u64 %0, t; }"
        : "=r"(a) : "l"(p));
    return a;
}
__device__ __forceinline__ void cp16(uint32_t dst, const void* src) {
    asm volatile("cp.async.cg.shared.global [%0], [%1], 16;"
                 :: "r"(dst), "l"(src) : "memory");
}
__device__ __forceinline__ void ldsm4(uint32_t* r, uint32_t addr) {
    asm volatile("ldmatrix.sync.aligned.m8n8.x4.shared.b16 {%0,%1,%2,%3}, [%4];"
                 : "=r"(r[0]), "=r"(r[1]), "=r"(r[2]), "=r"(r[3]) : "r"(addr));
}
__device__ __forceinline__ void imma(int* c, const uint32_t* a,
                                     uint32_t b0, uint32_t b1) {
    asm volatile("mma.sync.aligned.m16n8k32.row.col.s32.s8.s8.s32 "
                 "{%0,%1,%2,%3}, {%4,%5,%6,%7}, {%8,%9}, {%0,%1,%2,%3};"
                 : "+r"(c[0]), "+r"(c[1]), "+r"(c[2]), "+r"(c[3])
                 : "r"(a[0]), "r"(a[1]), "r"(a[2]), "r"(a[3]),
                   "r"(b0), "r"(b1));
}

__global__ void k_zero() { g_cnt = 0; }

// ---------------------------------------------------------------------------
// Kernel 1: conv1 dw + pw + sign + maxpool, one image per block.
// ---------------------------------------------------------------------------
__global__ __launch_bounds__(256) void k_conv1(
    const float* __restrict__ x,
    const float* __restrict__ w1dw, const float* __restrict__ b1dw,
    const float* __restrict__ w1pw, const float* __restrict__ b1pw)
{
    __shared__ float sx[3][32][32];
    __shared__ float sdw[3][32][32];
    __shared__ float swdw[27];
    __shared__ float sbdw[3];
    __shared__ float swpw[128 * 3];
    __shared__ float sbpw[128];

    const int n = blockIdx.x, tid = threadIdx.x;

    for (int i = tid; i < 3072; i += 256) ((float*)sx)[i] = x[n * 3072 + i];
    if (tid < 27)  swdw[tid] = fsign(w1dw[tid]);
    if (tid < 3)   sbdw[tid] = fsign(b1dw[tid]);
    for (int i = tid; i < 384; i += 256) swpw[i] = fsign(w1pw[i]);
    if (tid < 128) sbpw[tid] = fsign(b1pw[tid]);
    __syncthreads();

    for (int i = tid; i < 3072; i += 256) {
        int c = i >> 10, p = i & 1023, y = p >> 5, xx = p & 31;
        float acc = 0.f;
#pragma unroll
        for (int ky = 0; ky < 3; ky++) {
#pragma unroll
            for (int kx = 0; kx < 3; kx++) {
                int yy = y + ky - 1, xw = xx + kx - 1;
                if (yy >= 0 && yy < 32 && xw >= 0 && xw < 32)
                    acc += swdw[c * 9 + ky * 3 + kx] * sx[c][yy][xw];
            }
        }
        acc += sbdw[c];
        ((float*)sdw)[i] = acc;
    }
    __syncthreads();

    for (int i = tid; i < 32768; i += 256) {
        int oc = i & 127, pp = i >> 7;
        int oy = pp >> 4, ox = pp & 15;
        float w0 = swpw[oc * 3 + 0], w1 = swpw[oc * 3 + 1],
              w2 = swpw[oc * 3 + 2], bb = sbpw[oc];
        float vmax = -1e30f;
#pragma unroll
        for (int d = 0; d < 4; d++) {
            int y = 2 * oy + (d >> 1), xw = 2 * ox + (d & 1);
            float v = w0 * sdw[0][y][xw] + w1 * sdw[1][y][xw]
                    + w2 * sdw[2][y][xw] + bb;
            vmax = fmaxf(vmax, v);
        }
        g_a1[n * 32768 + pp * 128 + oc] = (int8_t)(int)fsign(vmax);
    }
}

// ---------------------------------------------------------------------------
// Kernel 2: conv2.  dw via u32 load + 4 masked dp4a per tap (exact int),
// pw via dp4a, sign + pool, one image per block.
// smem: [0,32768) a1 / a2-out; [32768,65536) t; [65536,98304) pw weights;
//       [98304,102912) dw selector words u32[32][9][4]; then biases.
// ---------------------------------------------------------------------------
static constexpr int C2_SMEM = 103424;

__global__ __launch_bounds__(256) void k_conv2(
    const float* __restrict__ w2dw, const float* __restrict__ b2dw,
    const float* __restrict__ w2pw, const float* __restrict__ b2pw)
{
    extern __shared__ char sm[];
    int8_t*   s_a1 = (int8_t*)sm;
    int8_t*   s_t  = (int8_t*)(sm + 32768);
    int8_t*   s_w  = (int8_t*)(sm + 65536);
    uint32_t* s_pk = (uint32_t*)(sm + 98304);   // [c4][tap][ch]
    int8_t*   s_bd = (int8_t*)(sm + 102912);
    int8_t*   s_bp = (int8_t*)(sm + 103040);

    const int n = blockIdx.x, tid = threadIdx.x;

    {
        const uint4* src = (const uint4*)(g_a1 + n * 32768);
        uint4* dst = (uint4*)s_a1;
        for (int i = tid; i < 2048; i += 256) dst[i] = src[i];
    }
    // dw selector words: byte ch of word = sign(w2dw[(c4*4+ch)*9 + tap])
    for (int i = tid; i < 1152; i += 256) {
        int c4 = i / 36, rem = i % 36, tap = rem >> 2, ch = rem & 3;
        int s = (int)fsign(w2dw[(c4 * 4 + ch) * 9 + tap]);
        s_pk[(c4 * 9 + tap) * 4 + ch] = ((uint32_t)(uint8_t)(char)s) << (8 * ch);
    }
    for (int i = tid; i < 32768; i += 256) s_w[i] = (int8_t)(int)fsign(w2pw[i]);
    if (tid < 128) s_bd[tid] = (int8_t)(int)fsign(b2dw[tid]);
    s_bp[tid] = (int8_t)(int)fsign(b2pw[tid]);
    __syncthreads();

    // depthwise 3x3 pad=1, 4 channels per thread-step, exact int dp4a
    for (int i = tid; i < 8192; i += 256) {
        int c4 = i & 31, p = i >> 5, y = p >> 4, xx = p & 15;
        int a0 = (int)s_bd[c4 * 4 + 0], a1 = (int)s_bd[c4 * 4 + 1];
        int a2 = (int)s_bd[c4 * 4 + 2], a3 = (int)s_bd[c4 * 4 + 3];
        const uint32_t* pk = s_pk + c4 * 36;
#pragma unroll
        for (int ky = 0; ky < 3; ky++) {
#pragma unroll
            for (int kx = 0; kx < 3; kx++) {
                int yy = y + ky - 1, xw = xx + kx - 1;
                if (yy >= 0 && yy < 16 && xw >= 0 && xw < 16) {
                    int A = *(const int*)(s_a1 + (yy * 16 + xw) * 128 + c4 * 4);
                    const int tap = ky * 3 + kx;
                    a0 = __dp4a(A, (int)pk[tap * 4 + 0], a0);
                    a1 = __dp4a(A, (int)pk[tap * 4 + 1], a1);
                    a2 = __dp4a(A, (int)pk[tap * 4 + 2], a2);
                    a3 = __dp4a(A, (int)pk[tap * 4 + 3], a3);
                }
            }
        }
        *(char4*)(s_t + p * 128 + c4 * 4) =
            make_char4((char)a0, (char)a1, (char)a2, (char)a3);
    }
    __syncthreads();

    // pointwise 128->256 via dp4a; thread == output channel; sign+pool
    {
        const int oc = tid;
        uint32_t wreg[32];
        const uint32_t* wsrc = (const uint32_t*)s_w + oc * 32;
#pragma unroll
        for (int j = 0; j < 32; j++) wreg[j] = wsrc[j];
        const int bb = (int)s_bp[oc];
        int8_t* s_a2 = s_a1;
        const uint4* t4 = (const uint4*)s_t;

        for (int q = 0; q < 64; q++) {
            int py = q >> 3, px = q & 7;
            int vmax = -2000000000;
#pragma unroll
            for (int d = 0; d < 4; d++) {
                int p = (2 * py + (d >> 1)) * 16 + 2 * px + (d & 1);
                int acc = bb;
#pragma unroll
                for (int jj = 0; jj < 8; jj++) {
                    uint4 t = t4[p * 8 + jj];
                    acc = __dp4a((int)t.x, (int)wreg[jj * 4 + 0], acc);
                    acc = __dp4a((int)t.y, (int)wreg[jj * 4 + 1], acc);
                    acc = __dp4a((int)t.z, (int)wreg[jj * 4 + 2], acc);
                    acc = __dp4a((int)t.w, (int)wreg[jj * 4 + 3], acc);
                }
                vmax = max(vmax, acc);
            }
            s_a2[oc * 64 + q] = (int8_t)isign(vmax);
        }
    }
    __syncthreads();

    {
        uint4* g = (uint4*)(g_a2 + n * 16384);
        const uint4* s2 = (const uint4*)s_a1;
        for (int i = tid; i < 1024; i += 256) g[i] = s2[i];
    }
}

// ---------------------------------------------------------------------------
// Kernel W: 2 balanced base-128 digit planes of round(w*2^18) + residual R_j.
// ---------------------------------------------------------------------------
__global__ __launch_bounds__(256) void k_wsplit(const float* __restrict__ W)
{
    __shared__ double rs[256];
    const int j = blockIdx.x, tid = threadIdx.x;
    const float4* W4 = (const float4*)(W + (size_t)j * 16384);
    char4* P0 = (char4*)(g_w1d + (size_t)j * 16384);
    char4* P1 = (char4*)(g_w1d + (1ull << 24) + (size_t)j * 16384);

    double part = 0.0;
    const double inv = 1.0 / 262144.0;
#pragma unroll 4
    for (int it = 0; it < 16; it++) {
        const int k4 = tid + (it << 8);
        float4 w = W4[k4];
        float wv[4] = {w.x, w.y, w.z, w.w};
        char dd0[4], dd1[4];
#pragma unroll
        for (int c = 0; c < 4; c++) {
            int n = __float2int_rn(wv[c] * 262144.0f);
            int d0 = (n + 64) >> 7;
            d0 = max(-127, min(127, d0));
            int d1 = n - (d0 << 7);
            d1 = max(-127, min(127, d1));
            int recon = (d0 << 7) + d1;
            part += fabs((double)wv[c] - (double)recon * inv);
            dd0[c] = (char)d0; dd1[c] = (char)d1;
        }
        P0[k4] = make_char4(dd0[0], dd0[1], dd0[2], dd0[3]);
        P1[k4] = make_char4(dd1[0], dd1[1], dd1[2], dd1[3]);
    }
    rs[tid] = part;
    __syncthreads();
    for (int s = 128; s; s >>= 1) {
        if (tid < s) rs[tid] += rs[tid + s];
        __syncthreads();
    }
    if (tid == 0) g_R[j] = (float)(rs[0] * 1.000001 + 1e-12);
}

// ---------------------------------------------------------------------------
// Kernel 3: fc1 IMMA GEMM, split-K.  Grid (8 n-tiles, 8 m-tiles, 2 kslices).
// CTA: 128m x 256n, K=8192 (64 its of BK=128), 4-stage cp.async (192KB),
// 8 warps of 64x64 -- identical inner structure to the R10 kernel that
// measured 226 MAC/cyc/SM.  Writes s32 partial to g_s32k[kslice].
// ---------------------------------------------------------------------------
static constexpr int ST_A  = 16384;     // 128 rows * 128B
static constexpr int ST_SZ = 49152;     // + 256 rows * 128B for B

__device__ __forceinline__ void gemm_load_stage(
    uint32_t stage, const int8_t* Ag, const int8_t* Bg, int kt, int tid)
{
    const int k0 = kt << 7;
#pragma unroll
    for (int r = 0; r < 4; r++) {           // A: 1024 16B chunks
        int c = tid + (r << 8);
        int row = c >> 3, seg = (c & 7) << 4;
        uint32_t dst = stage + row * 128 + (seg ^ ((row & 7) << 4));
        cp16(dst, Ag + (size_t)row * 16384 + k0 + seg);
    }
#pragma unroll
    for (int r = 0; r < 8; r++) {           // B: 2048 16B chunks
        int c = tid + (r << 8);
        int row = c >> 3, seg = (c & 7) << 4;
        uint32_t dst = stage + ST_A + row * 128 + (seg ^ ((row & 7) << 4));
        cp16(dst, Bg + (size_t)row * 16384 + k0 + seg);
    }
}

__global__ __launch_bounds__(256, 1) void k_fc1imma()
{
    extern __shared__ char sm[];
    const uint32_t smb = smem_u32(sm);

    const int tid = threadIdx.x, wid = tid >> 5, l = tid & 31;
    const int n0 = blockIdx.x * 256, m0 = blockIdx.y * 128;
    const int ks = blockIdx.z;
    const int warp_m = wid & 1, warp_n = wid >> 1;

    const int8_t* Ag = g_a2  + (size_t)m0 * 16384 + (size_t)ks * 8192;
    const int8_t* Bg = g_w1d + (size_t)n0 * 16384 + (size_t)ks * 8192;

    const int rowA = l & 15;
    const uint32_t cA = (uint32_t)(((l >> 4) << 4) ^ ((l & 7) << 4));
    const int rowB = (l & 7) + ((l >> 4) << 3);
    const uint32_t cB = (uint32_t)((((l >> 3) & 1) << 4) ^ ((l & 7) << 4));
    const uint32_t aBase = (uint32_t)((warp_m * 64 + rowA) * 128);
    const uint32_t bBase = (uint32_t)(ST_A + (warp_n * 64 + rowB) * 128);

    int c[4][8][4];
#pragma unroll
    for (int i = 0; i < 4; i++)
#pragma unroll
        for (int nn = 0; nn < 8; nn++)
#pragma unroll
            for (int q = 0; q < 4; q++) c[i][nn][q] = 0;

    gemm_load_stage(smb + 0 * ST_SZ, Ag, Bg, 0, tid);
    asm volatile("cp.async.commit_group;" ::: "memory");
    gemm_load_stage(smb + 1 * ST_SZ, Ag, Bg, 1, tid);
    asm volatile("cp.async.commit_group;" ::: "memory");
    gemm_load_stage(smb + 2 * ST_SZ, Ag, Bg, 2, tid);
    asm volatile("cp.async.commit_group;" ::: "memory");

    for (int it = 0; it < 64; it++) {
        asm volatile("cp.async.wait_group 2;" ::: "memory");
        __syncthreads();
        if (it + 3 < 64)
            gemm_load_stage(smb + ((it + 3) & 3) * ST_SZ, Ag, Bg, it + 3, tid);
        asm volatile("cp.async.commit_group;" ::: "memory");

        const uint32_t buf = smb + (it & 3) * ST_SZ;
#pragma unroll
        for (int kk = 0; kk < 4; kk++) {
            const uint32_t ka = ((uint32_t)(kk << 5)) ^ cA;
            const uint32_t kb = ((uint32_t)(kk << 5)) ^ cB;
            uint32_t a[4][4], b[4][4];
#pragma unroll
            for (int i = 0; i < 4; i++)
                ldsm4(a[i], buf + aBase + i * 2048 + ka);
#pragma unroll
            for (int t = 0; t < 4; t++)
                ldsm4(b[t], buf + bBase + t * 2048 + kb);
#pragma unroll
            for (int i = 0; i < 4; i++)
#pragma unroll
                for (int t = 0; t < 4; t++) {
                    imma(c[i][2 * t],     a[i], b[t][0], b[t][1]);
                    imma(c[i][2 * t + 1], a[i], b[t][2], b[t][3]);
                }
        }
    }
    __syncthreads();

    // epilogue: frags -> smem [128][260] -> coalesced global partial
    int* so = (int*)sm;
    const int gm = l >> 2, gn = (l & 3) << 1;
#pragma unroll
    for (int i = 0; i < 4; i++) {
        int ml = warp_m * 64 + i * 16 + gm;
#pragma unroll
        for (int nn = 0; nn < 8; nn++) {
            int nl = warp_n * 64 + nn * 8 + gn;
            so[ml * 260 + nl]           = c[i][nn][0];
            so[ml * 260 + nl + 1]       = c[i][nn][1];
            so[(ml + 8) * 260 + nl]     = c[i][nn][2];
            so[(ml + 8) * 260 + nl + 1] = c[i][nn][3];
        }
    }
    __syncthreads();
    {
        int* gp = g_s32k + (size_t)ks * 2097152 + (size_t)m0 * 2048 + n0;
        for (int i = tid; i < 32768; i += 256) {
            int ml = i >> 8, nl = i & 255;
            gp[(size_t)ml * 2048 + nl] = so[ml * 260 + nl];
        }
    }
}

// ---------------------------------------------------------------------------
// Kernel 3b: sum kslices, recombine digit planes + bias; sign if |v| > R_j,
// else push onto worklist.  One block per m.
// ---------------------------------------------------------------------------
__global__ __launch_bounds__(256) void k_recflag(const float* __restrict__ bf)
{
    __shared__ int s_cnt, s_base;
    __shared__ int s_list[1024];

    const int m = blockIdx.x, t = threadIdx.x;
    if (t == 0) s_cnt = 0;
    __syncthreads();

    const int* b0 = g_s32k + (size_t)m * 2048;
    const int* b1 = g_s32k + 2097152ull + (size_t)m * 2048;
    const int4 h0 = ((const int4*)b0)[t];            // plane0, kslice0
    const int4 h1 = ((const int4*)(b0 + 1024))[t];   // plane1, kslice0
    const int4 g0 = ((const int4*)b1)[t];            // plane0, kslice1
    const int4 g1 = ((const int4*)(b1 + 1024))[t];   // plane1, kslice1
    const float4 bb = ((const float4*)bf)[t];
    const float4 Rr = ((const float4*)g_R)[t];

    int sv[4] = {h0.x + g0.x, h0.y + g0.y, h0.z + g0.z, h0.w + g0.w};
    int lv[4] = {h1.x + g1.x, h1.y + g1.y, h1.z + g1.z, h1.w + g1.w};
    float bv[4] = {bb.x, bb.y, bb.z, bb.w};
    float Rv[4] = {Rr.x, Rr.y, Rr.z, Rr.w};

    const double inv = 1.0 / 262144.0;
    char o[4];
#pragma unroll
    for (int cix = 0; cix < 4; cix++) {
        long long S = ((long long)sv[cix] << 7) + lv[cix];
        double v = (double)S * inv + (double)bv[cix];
        o[cix] = (char)((v > 0.0) ? 1 : ((v < 0.0) ? -1 : 0));
        if (fabs(v) <= (double)Rv[cix]) {
            int p = atomicAdd(&s_cnt, 1);
            s_list[p] = m * 1024 + t * 4 + cix;
        }
    }
    ((char4*)g_a3)[m * 256 + t] = make_char4(o[0], o[1], o[2], o[3]);
    __syncthreads();

    if (t == 0 && s_cnt > 0) s_base = atomicAdd(&g_cnt, s_cnt);
    __syncthreads();
    for (int i = t; i < s_cnt; i += 256) g_list[s_base + i] = s_list[i];
}

// ---------------------------------------------------------------------------
// Kernel 3c: fp64 exact recompute of flagged pairs (4 independent chains).
// ---------------------------------------------------------------------------
__global__ __launch_bounds__(256) void k_fixup(
    const float* __restrict__ W, const float* __restrict__ bf)
{
    __shared__ double rs[256];
    const int t = threadIdx.x;
    const int cnt = g_cnt;

    for (int e = blockIdx.x; e < cnt; e += gridDim.x) {
        const int pair = g_list[e];
        const int m = pair >> 10, j = pair & 1023;
        const float* wr = W + (size_t)j * 16384;
        const int8_t* ar = g_a2 + (size_t)m * 16384;

        double a0 = 0.0, a1 = 0.0, a2 = 0.0, a3 = 0.0;
#pragma unroll 4
        for (int k = t; k < 16384; k += 1024) {
            a0 += (double)wr[k]        * (double)ar[k];
            a1 += (double)wr[k + 256]  * (double)ar[k + 256];
            a2 += (double)wr[k + 512]  * (double)ar[k + 512];
            a3 += (double)wr[k + 768]  * (double)ar[k + 768];
        }
        rs[t] = (a0 + a1) + (a2 + a3);
        __syncthreads();
        for (int s = 128; s; s >>= 1) {
            if (t < s) rs[t] += rs[t + s];
            __syncthreads();
        }
        if (t == 0) {
            double v = rs[0] + (double)bf[j];
            g_a3[(size_t)m * 1024 + j] =
                (char)((v > 0.0) ? 1 : ((v < 0.0) ? -1 : 0));
        }
        __syncthreads();
    }
}

// ---------------------------------------------------------------------------
// Kernel 4: fc2  out[1024][10] = a3 @ W2^T + b2
// ---------------------------------------------------------------------------
__global__ __launch_bounds__(128) void k_fc2(
    const float* __restrict__ W2, const float* __restrict__ b2,
    float* __restrict__ out)
{
    const int n = blockIdx.x, tid = threadIdx.x;
    float acc[10] = {};
    const int8_t* a = g_a3 + n * 1024;
    for (int k = tid; k < 1024; k += 128) {
        float s = (float)a[k];
#pragma unroll
        for (int j = 0; j < 10; j++) acc[j] += s * W2[j * 1024 + k];
    }
#pragma unroll
    for (int j = 0; j < 10; j++)
#pragma unroll
        for (int off = 16; off; off >>= 1)
            acc[j] += __shfl_down_sync(0xffffffffu, acc[j], off);

    __shared__ float red[4][10];
    int w = tid >> 5, lm = tid & 31;
    if (lm == 0)
#pragma unroll
        for (int j = 0; j < 10; j++) red[w][j] = acc[j];
    __syncthreads();
    if (tid < 10) {
        float v = red[0][tid] + red[1][tid] + red[2][tid] + red[3][tid] + b2[tid];
        out[n * 10 + tid] = v;
    }
}

// ---------------------------------------------------------------------------
extern "C" void kernel_launch(void* const* d_in, const int* in_sizes, int n_in,
                              void* d_out, int out_size)
{
    const float* x    = (const float*)d_in[0];
    const float* w1dw = (const float*)d_in[1];
    const float* b1dw = (const float*)d_in[2];
    const float* w1pw = (const float*)d_in[3];
    const float* b1pw = (const float*)d_in[4];
    const float* w2dw = (const float*)d_in[5];
    const float* b2dw = (const float*)d_in[6];
    const float* w2pw = (const float*)d_in[7];
    const float* b2pw = (const float*)d_in[8];
    const float* fc1w = (const float*)d_in[9];
    const float* fc1b = (const float*)d_in[10];
    const float* fc2w = (const float*)d_in[11];
    const float* fc2b = (const float*)d_in[12];
    float* out = (float*)d_out;

    cudaFuncSetAttribute(k_conv2, cudaFuncAttributeMaxDynamicSharedMemorySize, C2_SMEM);
    const int SMEMG = 4 * ST_SZ;   // 196608
    cudaFuncSetAttribute(k_fc1imma, cudaFuncAttributeMaxDynamicSharedMemorySize, SMEMG);

    k_zero<<<1, 1>>>();
    k_wsplit<<<1024, 256>>>(fc1w);
    k_conv1<<<1024, 256>>>(x, w1dw, b1dw, w1pw, b1pw);
    k_conv2<<<1024, 256, C2_SMEM>>>(w2dw, b2dw, w2pw, b2pw);
    k_fc1imma<<<dim3(8, 8, 2), 256, SMEMG>>>();
    k_recflag<<<1024, 256>>>(fc1b);
    k_fixup<<<2048, 256>>>(fc1w, fc1b);
    k_fc2<<<1024, 128>>>(fc2w, fc2b, out);
}

// round 14
// speedup vs baseline: 2.5927x; 2.3595x over previous
#include <cuda_runtime.h>
#include <cstdint>

// ---------------------------------------------------------------------------
// BinaryConnectNet forward (compute_103-safe: mma.sync/ldmatrix/cp.async).
//  conv1: dw3x3(g=3)+pw1x1(3->128), sign, maxpool2 -> a1 int8
//  conv2: dw dp4a + pw dp4a + sign + pool          -> a2 int8 (+-1)
//  fc1:   w -> n18=round(w*2^18) split into 2 int8 digits (planes 0,1) for the
//         IMMA GEMM, plus r32 = round(w*2^32)-n18*2^14 split into 2 more int8
//         digits (planes 2,3) for an exact dp4a correction.  Tiered sign:
//           tier1: |S01*2^14 + B32| > R1_j  (int64)        -> sign certain
//           tier2: + dp4a planes 2,3 -> T; |T| > 8196      -> sign certain
//           tier3: fp64 dot with true fp32 weights (few entries)
//  fc2:   a3 @ W2^T + b2 -> out [1024][10] fp32
//  NO bulk fp64 anywhere in the fc1 path (differential vs R12/R13).
// ---------------------------------------------------------------------------

__device__ int8_t g_a1[1024 * 256 * 128];
__device__ int8_t g_a2[1024 * 16384];
__device__ int8_t g_a3[1024 * 1024];
__device__ int8_t g_w1d[4ull * 1024 * 16384];   // [plane][j][k]
__device__ int    g_s32k[2ull * 1024 * 2048];   // [kslice][m][n']
__device__ int    g_R1[1024];                   // per-j tier1 bound (2^-32 units)
__device__ int    g_cnt,  g_cnt2;
__device__ int    g_list[1024 * 1024];
__device__ int    g_list2[1024 * 1024];

__device__ __forceinline__ float fsign(float v) {
    return (v > 0.f) ? 1.f : ((v < 0.f) ? -1.f : 0.f);
}
__device__ __forceinline__ int isign(int v) { return (v > 0) - (v < 0); }

__device__ __forceinline__ uint32_t smem_u32(const void* p) {
    uint32_t a;
    asm("{ .reg .u64 t; cvta.to.shared.u64 t, %1; cvt.u32.u64 %0, t; }"
        : "=r"(a) : "l"(p));
    return a;
}
__device__ __forceinline__ void cp16(uint32_t dst, const void* src) {
    asm volatile("cp.async.cg.shared.global [%0], [%1], 16;"
                 :: "r"(dst), "l"(src) : "memory");
}
__device__ __forceinline__ void ldsm4(uint32_t* r, uint32_t addr) {
    asm volatile("ldmatrix.sync.aligned.m8n8.x4.shared.b16 {%0,%1,%2,%3}, [%4];"
                 : "=r"(r[0]), "=r"(r[1]), "=r"(r[2]), "=r"(r[3]) : "r"(addr));
}
__device__ __forceinline__ void imma(int* c, const uint32_t* a,
                                     uint32_t b0, uint32_t b1) {
    asm volatile("mma.sync.aligned.m16n8k32.row.col.s32.s8.s8.s32 "
                 "{%0,%1,%2,%3}, {%4,%5,%6,%7}, {%8,%9}, {%0,%1,%2,%3};"
                 : "+r"(c[0]), "+r"(c[1]), "+r"(c[2]), "+r"(c[3])
                 : "r"(a[0]), "r"(a[1]), "r"(a[2]), "r"(a[3]),
                   "r"(b0), "r"(b1));
}

__global__ void k_zero() { g_cnt = 0; g_cnt2 = 0; }

// ---------------------------------------------------------------------------
// Kernel 1: conv1 dw + pw + sign + maxpool, one image per block.
// ---------------------------------------------------------------------------
__global__ __launch_bounds__(256) void k_conv1(
    const float* __restrict__ x,
    const float* __restrict__ w1dw, const float* __restrict__ b1dw,
    const float* __restrict__ w1pw, const float* __restrict__ b1pw)
{
    __shared__ float sx[3][32][32];
    __shared__ float sdw[3][32][32];
    __shared__ float swdw[27];
    __shared__ float sbdw[3];
    __shared__ float swpw[128 * 3];
    __shared__ float sbpw[128];

    const int n = blockIdx.x, tid = threadIdx.x;

    for (int i = tid; i < 3072; i += 256) ((float*)sx)[i] = x[n * 3072 + i];
    if (tid < 27)  swdw[tid] = fsign(w1dw[tid]);
    if (tid < 3)   sbdw[tid] = fsign(b1dw[tid]);
    for (int i = tid; i < 384; i += 256) swpw[i] = fsign(w1pw[i]);
    if (tid < 128) sbpw[tid] = fsign(b1pw[tid]);
    __syncthreads();

    for (int i = tid; i < 3072; i += 256) {
        int c = i >> 10, p = i & 1023, y = p >> 5, xx = p & 31;
        float acc = 0.f;
#pragma unroll
        for (int ky = 0; ky < 3; ky++) {
#pragma unroll
            for (int kx = 0; kx < 3; kx++) {
                int yy = y + ky - 1, xw = xx + kx - 1;
                if (yy >= 0 && yy < 32 && xw >= 0 && xw < 32)
                    acc += swdw[c * 9 + ky * 3 + kx] * sx[c][yy][xw];
            }
        }
        acc += sbdw[c];
        ((float*)sdw)[i] = acc;
    }
    __syncthreads();

    for (int i = tid; i < 32768; i += 256) {
        int oc = i & 127, pp = i >> 7;
        int oy = pp >> 4, ox = pp & 15;
        float w0 = swpw[oc * 3 + 0], w1 = swpw[oc * 3 + 1],
              w2 = swpw[oc * 3 + 2], bb = sbpw[oc];
        float vmax = -1e30f;
#pragma unroll
        for (int d = 0; d < 4; d++) {
            int y = 2 * oy + (d >> 1), xw = 2 * ox + (d & 1);
            float v = w0 * sdw[0][y][xw] + w1 * sdw[1][y][xw]
                    + w2 * sdw[2][y][xw] + bb;
            vmax = fmaxf(vmax, v);
        }
        g_a1[n * 32768 + pp * 128 + oc] = (int8_t)(int)fsign(vmax);
    }
}

// ---------------------------------------------------------------------------
// Kernel 2: conv2 (R13 version — dw via masked dp4a, pw via dp4a).
// ---------------------------------------------------------------------------
static constexpr int C2_SMEM = 103424;

__global__ __launch_bounds__(256) void k_conv2(
    const float* __restrict__ w2dw, const float* __restrict__ b2dw,
    const float* __restrict__ w2pw, const float* __restrict__ b2pw)
{
    extern __shared__ char sm[];
    int8_t*   s_a1 = (int8_t*)sm;
    int8_t*   s_t  = (int8_t*)(sm + 32768);
    int8_t*   s_w  = (int8_t*)(sm + 65536);
    uint32_t* s_pk = (uint32_t*)(sm + 98304);
    int8_t*   s_bd = (int8_t*)(sm + 102912);
    int8_t*   s_bp = (int8_t*)(sm + 103040);

    const int n = blockIdx.x, tid = threadIdx.x;

    {
        const uint4* src = (const uint4*)(g_a1 + n * 32768);
        uint4* dst = (uint4*)s_a1;
        for (int i = tid; i < 2048; i += 256) dst[i] = src[i];
    }
    for (int i = tid; i < 1152; i += 256) {
        int c4 = i / 36, rem = i % 36, tap = rem >> 2, ch = rem & 3;
        int s = (int)fsign(w2dw[(c4 * 4 + ch) * 9 + tap]);
        s_pk[(c4 * 9 + tap) * 4 + ch] = ((uint32_t)(uint8_t)(char)s) << (8 * ch);
    }
    for (int i = tid; i < 32768; i += 256) s_w[i] = (int8_t)(int)fsign(w2pw[i]);
    if (tid < 128) s_bd[tid] = (int8_t)(int)fsign(b2dw[tid]);
    s_bp[tid] = (int8_t)(int)fsign(b2pw[tid]);
    __syncthreads();

    for (int i = tid; i < 8192; i += 256) {
        int c4 = i & 31, p = i >> 5, y = p >> 4, xx = p & 15;
        int a0 = (int)s_bd[c4 * 4 + 0], a1 = (int)s_bd[c4 * 4 + 1];
        int a2 = (int)s_bd[c4 * 4 + 2], a3 = (int)s_bd[c4 * 4 + 3];
        const uint32_t* pk = s_pk + c4 * 36;
#pragma unroll
        for (int ky = 0; ky < 3; ky++) {
#pragma unroll
            for (int kx = 0; kx < 3; kx++) {
                int yy = y + ky - 1, xw = xx + kx - 1;
                if (yy >= 0 && yy < 16 && xw >= 0 && xw < 16) {
                    int A = *(const int*)(s_a1 + (yy * 16 + xw) * 128 + c4 * 4);
                    const int tap = ky * 3 + kx;
                    a0 = __dp4a(A, (int)pk[tap * 4 + 0], a0);
                    a1 = __dp4a(A, (int)pk[tap * 4 + 1], a1);
                    a2 = __dp4a(A, (int)pk[tap * 4 + 2], a2);
                    a3 = __dp4a(A, (int)pk[tap * 4 + 3], a3);
                }
            }
        }
        *(char4*)(s_t + p * 128 + c4 * 4) =
            make_char4((char)a0, (char)a1, (char)a2, (char)a3);
    }
    __syncthreads();

    {
        const int oc = tid;
        uint32_t wreg[32];
        const uint32_t* wsrc = (const uint32_t*)s_w + oc * 32;
#pragma unroll
        for (int j = 0; j < 32; j++) wreg[j] = wsrc[j];
        const int bb = (int)s_bp[oc];
        int8_t* s_a2 = s_a1;
        const uint4* t4 = (const uint4*)s_t;

        for (int q = 0; q < 64; q++) {
            int py = q >> 3, px = q & 7;
            int vmax = -2000000000;
#pragma unroll
            for (int d = 0; d < 4; d++) {
                int p = (2 * py + (d >> 1)) * 16 + 2 * px + (d & 1);
                int acc = bb;
#pragma unroll
                for (int jj = 0; jj < 8; jj++) {
                    uint4 t = t4[p * 8 + jj];
                    acc = __dp4a((int)t.x, (int)wreg[jj * 4 + 0], acc);
                    acc = __dp4a((int)t.y, (int)wreg[jj * 4 + 1], acc);
                    acc = __dp4a((int)t.z, (int)wreg[jj * 4 + 2], acc);
                    acc = __dp4a((int)t.w, (int)wreg[jj * 4 + 3], acc);
                }
                vmax = max(vmax, acc);
            }
            s_a2[oc * 64 + q] = (int8_t)isign(vmax);
        }
    }
    __syncthreads();

    {
        uint4* g = (uint4*)(g_a2 + n * 16384);
        const uint4* s2 = (const uint4*)s_a1;
        for (int i = tid; i < 1024; i += 256) g[i] = s2[i];
    }
}

// ---------------------------------------------------------------------------
// Kernel W: 4 digit planes + int residual bound.  NO fp64.
//   n18 = rint(w*2^18)   (w*2^18 exact in fp32: pow2 scale)
//   planes 0,1: balanced base-128 digits of n18          (GEMM operand)
//   w32 = rint(w*2^32)   (exact via pow2 scale + cvt)
//   r32 = w32 - n18*2^14, |r32| <= 8192
//   planes 2,3: balanced base-128 digits of r32          (tier-2 correction)
//   R1_j = sum|r32| + 8192 + 4   (covers frac parts + bias rounding)
// ---------------------------------------------------------------------------
__global__ __launch_bounds__(256) void k_wsplit(const float* __restrict__ W)
{
    __shared__ int rs[256];
    const int j = blockIdx.x, tid = threadIdx.x;
    const float4* W4 = (const float4*)(W + (size_t)j * 16384);
    char4* P0 = (char4*)(g_w1d + 0ull * 16777216 + (size_t)j * 16384);
    char4* P1 = (char4*)(g_w1d + 1ull * 16777216 + (size_t)j * 16384);
    char4* P2 = (char4*)(g_w1d + 2ull * 16777216 + (size_t)j * 16384);
    char4* P3 = (char4*)(g_w1d + 3ull * 16777216 + (size_t)j * 16384);

    int racc = 0;
#pragma unroll 4
    for (int it = 0; it < 16; it++) {
        const int k4 = tid + (it << 8);
        float4 w = W4[k4];
        float wv[4] = {w.x, w.y, w.z, w.w};
        char dd0[4], dd1[4], dd2[4], dd3[4];
#pragma unroll
        for (int c = 0; c < 4; c++) {
            int n18 = __float2int_rn(wv[c] * 262144.0f);
            n18 = max(-16256, min(16256, n18));
            int d0 = (n18 + 64) >> 7;
            int d1 = n18 - (d0 << 7);
            int w32 = __float2int_rn(wv[c] * 4294967296.0f);
            int r32 = w32 - (n18 << 14);
            int d2 = (r32 + 64) >> 7;
            d2 = max(-127, min(127, d2));
            int d3 = r32 - (d2 << 7);
            d3 = max(-127, min(127, d3));
            racc += abs(r32);
            dd0[c] = (char)d0; dd1[c] = (char)d1;
            dd2[c] = (char)d2; dd3[c] = (char)d3;
        }
        P0[k4] = make_char4(dd0[0], dd0[1], dd0[2], dd0[3]);
        P1[k4] = make_char4(dd1[0], dd1[1], dd1[2], dd1[3]);
        P2[k4] = make_char4(dd2[0], dd2[1], dd2[2], dd2[3]);
        P3[k4] = make_char4(dd3[0], dd3[1], dd3[2], dd3[3]);
    }
    rs[tid] = racc;
    __syncthreads();
    for (int s = 128; s; s >>= 1) {
        if (tid < s) rs[tid] += rs[tid + s];
        __syncthreads();
    }
    if (tid == 0) g_R1[j] = rs[0] + 8192 + 4;
}

// ---------------------------------------------------------------------------
// Kernel 3: fc1 IMMA GEMM on planes 0,1.  Split-K, R10-proven tile shape.
// Grid (8 n-tiles, 8 m-tiles, 2 kslices).  CTA 128m x 256n, 64 its of BK=128.
// ---------------------------------------------------------------------------
static constexpr int ST_A  = 16384;
static constexpr int ST_SZ = 49152;

__device__ __forceinline__ void gemm_load_stage(
    uint32_t stage, const int8_t* Ag, const int8_t* Bg, int kt, int tid)
{
    const int k0 = kt << 7;
#pragma unroll
    for (int r = 0; r < 4; r++) {
        int c = tid + (r << 8);
        int row = c >> 3, seg = (c & 7) << 4;
        uint32_t dst = stage + row * 128 + (seg ^ ((row & 7) << 4));
        cp16(dst, Ag + (size_t)row * 16384 + k0 + seg);
    }
#pragma unroll
    for (int r = 0; r < 8; r++) {
        int c = tid + (r << 8);
        int row = c >> 3, seg = (c & 7) << 4;
        uint32_t dst = stage + ST_A + row * 128 + (seg ^ ((row & 7) << 4));
        cp16(dst, Bg + (size_t)row * 16384 + k0 + seg);
    }
}

__global__ __launch_bounds__(256, 1) void k_fc1imma()
{
    extern __shared__ char sm[];
    const uint32_t smb = smem_u32(sm);

    const int tid = threadIdx.x, wid = tid >> 5, l = tid & 31;
    const int n0 = blockIdx.x * 256, m0 = blockIdx.y * 128;
    const int ks = blockIdx.z;
    const int warp_m = wid & 1, warp_n = wid >> 1;

    const int8_t* Ag = g_a2  + (size_t)m0 * 16384 + (size_t)ks * 8192;
    const int8_t* Bg = g_w1d + (size_t)n0 * 16384 + (size_t)ks * 8192;

    const int rowA = l & 15;
    const uint32_t cA = (uint32_t)(((l >> 4) << 4) ^ ((l & 7) << 4));
    const int rowB = (l & 7) + ((l >> 4) << 3);
    const uint32_t cB = (uint32_t)((((l >> 3) & 1) << 4) ^ ((l & 7) << 4));
    const uint32_t aBase = (uint32_t)((warp_m * 64 + rowA) * 128);
    const uint32_t bBase = (uint32_t)(ST_A + (warp_n * 64 + rowB) * 128);

    int c[4][8][4];
#pragma unroll
    for (int i = 0; i < 4; i++)
#pragma unroll
        for (int nn = 0; nn < 8; nn++)
#pragma unroll
            for (int q = 0; q < 4; q++) c[i][nn][q] = 0;

    gemm_load_stage(smb + 0 * ST_SZ, Ag, Bg, 0, tid);
    asm volatile("cp.async.commit_group;" ::: "memory");
    gemm_load_stage(smb + 1 * ST_SZ, Ag, Bg, 1, tid);
    asm volatile("cp.async.commit_group;" ::: "memory");
    gemm_load_stage(smb + 2 * ST_SZ, Ag, Bg, 2, tid);
    asm volatile("cp.async.commit_group;" ::: "memory");

    for (int it = 0; it < 64; it++) {
        asm volatile("cp.async.wait_group 2;" ::: "memory");
        __syncthreads();
        if (it + 3 < 64)
            gemm_load_stage(smb + ((it + 3) & 3) * ST_SZ, Ag, Bg, it + 3, tid);
        asm volatile("cp.async.commit_group;" ::: "memory");

        const uint32_t buf = smb + (it & 3) * ST_SZ;
#pragma unroll
        for (int kk = 0; kk < 4; kk++) {
            const uint32_t ka = ((uint32_t)(kk << 5)) ^ cA;
            const uint32_t kb = ((uint32_t)(kk << 5)) ^ cB;
            uint32_t a[4][4], b[4][4];
#pragma unroll
            for (int i = 0; i < 4; i++)
                ldsm4(a[i], buf + aBase + i * 2048 + ka);
#pragma unroll
            for (int t = 0; t < 4; t++)
                ldsm4(b[t], buf + bBase + t * 2048 + kb);
#pragma unroll
            for (int i = 0; i < 4; i++)
#pragma unroll
                for (int t = 0; t < 4; t++) {
                    imma(c[i][2 * t],     a[i], b[t][0], b[t][1]);
                    imma(c[i][2 * t + 1], a[i], b[t][2], b[t][3]);
                }
        }
    }
    __syncthreads();

    int* so = (int*)sm;
    const int gm = l >> 2, gn = (l & 3) << 1;
#pragma unroll
    for (int i = 0; i < 4; i++) {
        int ml = warp_m * 64 + i * 16 + gm;
#pragma unroll
        for (int nn = 0; nn < 8; nn++) {
            int nl = warp_n * 64 + nn * 8 + gn;
            so[ml * 260 + nl]           = c[i][nn][0];
            so[ml * 260 + nl + 1]       = c[i][nn][1];
            so[(ml + 8) * 260 + nl]     = c[i][nn][2];
            so[(ml + 8) * 260 + nl + 1] = c[i][nn][3];
        }
    }
    __syncthreads();
    {
        int* gp = g_s32k + (size_t)ks * 2097152 + (size_t)m0 * 2048 + n0;
        for (int i = tid; i < 32768; i += 256) {
            int ml = i >> 8, nl = i & 255;
            gp[(size_t)ml * 2048 + nl] = so[ml * 260 + nl];
        }
    }
}

// ---------------------------------------------------------------------------
// Kernel 3b: tier-1.  V = S01*2^14 + B32 (int64).  |V| > R1_j -> sign.
// Else push to worklist.  One block per m.  NO fp64.
// ---------------------------------------------------------------------------
__global__ __launch_bounds__(256) void k_recflag(const float* __restrict__ bf)
{
    __shared__ int s_cnt, s_base;
    __shared__ int s_list[1024];

    const int m = blockIdx.x, t = threadIdx.x;
    if (t == 0) s_cnt = 0;
    __syncthreads();

    const int* b0 = g_s32k + (size_t)m * 2048;
    const int* b1 = g_s32k + 2097152ull + (size_t)m * 2048;
    const int4 h0 = ((const int4*)b0)[t];
    const int4 h1 = ((const int4*)(b0 + 1024))[t];
    const int4 g0 = ((const int4*)b1)[t];
    const int4 g1 = ((const int4*)(b1 + 1024))[t];
    const float4 bb = ((const float4*)bf)[t];
    const int4 Rr = ((const int4*)g_R1)[t];

    int sv[4] = {h0.x + g0.x, h0.y + g0.y, h0.z + g0.z, h0.w + g0.w};
    int lv[4] = {h1.x + g1.x, h1.y + g1.y, h1.z + g1.z, h1.w + g1.w};
    float bv[4] = {bb.x, bb.y, bb.z, bb.w};
    int Rv[4] = {Rr.x, Rr.y, Rr.z, Rr.w};

    char o[4] = {0, 0, 0, 0};
#pragma unroll
    for (int cix = 0; cix < 4; cix++) {
        long long S01 = ((long long)sv[cix] << 7) + lv[cix];
        long long B32 = __float2ll_rn(bv[cix] * 4294967296.0f);
        long long V = (S01 << 14) + B32;
        long long aV = (V < 0) ? -V : V;
        if (aV > (long long)Rv[cix]) {
            o[cix] = (char)((V > 0) ? 1 : -1);
        } else {
            int p = atomicAdd(&s_cnt, 1);
            s_list[p] = m * 1024 + t * 4 + cix;
        }
    }
    ((char4*)g_a3)[m * 256 + t] = make_char4(o[0], o[1], o[2], o[3]);
    __syncthreads();

    if (t == 0 && s_cnt > 0) s_base = atomicAdd(&g_cnt, s_cnt);
    __syncthreads();
    for (int i = t; i < s_cnt; i += 256) g_list[s_base + i] = s_list[i];
}

// ---------------------------------------------------------------------------
// Kernel 3c: tier-2.  One warp per entry; dp4a on planes 2,3 (exact).
//   T = S01*2^14 + S2*128 + S3 + B32.  |T| > 8196 -> sign; else list2.
// ---------------------------------------------------------------------------
__global__ __launch_bounds__(256) void k_fix2(const float* __restrict__ bf)
{
    const int tid = threadIdx.x, lane = tid & 31, w = tid >> 5;
    const int gw = blockIdx.x * 8 + w, stride = gridDim.x * 8;
    const int cnt = g_cnt;

    for (int e = gw; e < cnt; e += stride) {
        const int pair = g_list[e];
        const int m = pair >> 10, j = pair & 1023;
        const int* aw = (const int*)(g_a2 + (size_t)m * 16384);
        const int* p2 = (const int*)(g_w1d + 2ull * 16777216 + (size_t)j * 16384);
        const int* p3 = (const int*)(g_w1d + 3ull * 16777216 + (size_t)j * 16384);

        int s2 = 0, s3 = 0;
#pragma unroll 4
        for (int c = lane; c < 4096; c += 32) {
            int av = aw[c];
            s2 = __dp4a(p2[c], av, s2);
            s3 = __dp4a(p3[c], av, s3);
        }
#pragma unroll
        for (int off = 16; off; off >>= 1) {
            s2 += __shfl_xor_sync(0xffffffffu, s2, off);
            s3 += __shfl_xor_sync(0xffffffffu, s3, off);
        }
        if (lane == 0) {
            int S0 = g_s32k[(size_t)m * 2048 + j]
                   + g_s32k[2097152ull + (size_t)m * 2048 + j];
            int S1 = g_s32k[(size_t)m * 2048 + 1024 + j]
                   + g_s32k[2097152ull + (size_t)m * 2048 + 1024 + j];
            long long S01 = ((long long)S0 << 7) + S1;
            long long B32 = __float2ll_rn(bf[j] * 4294967296.0f);
            long long T = (S01 << 14) + (long long)s2 * 128 + s3 + B32;
            long long aT = (T < 0) ? -T : T;
            if (aT > 8196) {
                g_a3[(size_t)m * 1024 + j] = (char)((T > 0) ? 1 : -1);
            } else {
                int p = atomicAdd(&g_cnt2, 1);
                g_list2[p] = pair;
            }
        }
    }
}

// ---------------------------------------------------------------------------
// Kernel 3d: tier-3.  fp64 dot with true fp32 weights (expected ~0-8 entries).
// ---------------------------------------------------------------------------
__global__ __launch_bounds__(256) void k_fix3(
    const float* __restrict__ W, const float* __restrict__ bf)
{
    __shared__ double rs[256];
    const int t = threadIdx.x;
    const int cnt = g_cnt2;

    for (int e = blockIdx.x; e < cnt; e += gridDim.x) {
        const int pair = g_list2[e];
        const int m = pair >> 10, j = pair & 1023;
        const float* wr = W + (size_t)j * 16384;
        const int8_t* ar = g_a2 + (size_t)m * 16384;

        double a0 = 0.0, a1 = 0.0, a2 = 0.0, a3 = 0.0;
        for (int k = t; k < 16384; k += 1024) {
            a0 += (double)wr[k]       * (double)ar[k];
            a1 += (double)wr[k + 256] * (double)ar[k + 256];
            a2 += (double)wr[k + 512] * (double)ar[k + 512];
            a3 += (double)wr[k + 768] * (double)ar[k + 768];
        }
        rs[t] = (a0 + a1) + (a2 + a3);
        __syncthreads();
        for (int s = 128; s; s >>= 1) {
            if (t < s) rs[t] += rs[t + s];
            __syncthreads();
        }
        if (t == 0) {
            double v = rs[0] + (double)bf[j];
            g_a3[(size_t)m * 1024 + j] =
                (char)((v > 0.0) ? 1 : ((v < 0.0) ? -1 : 0));
        }
        __syncthreads();
    }
}

// ---------------------------------------------------------------------------
// Kernel 4: fc2  out[1024][10] = a3 @ W2^T + b2
// ---------------------------------------------------------------------------
__global__ __launch_bounds__(128) void k_fc2(
    const float* __restrict__ W2, const float* __restrict__ b2,
    float* __restrict__ out)
{
    const int n = blockIdx.x, tid = threadIdx.x;
    float acc[10] = {};
    const int8_t* a = g_a3 + n * 1024;
    for (int k = tid; k < 1024; k += 128) {
        float s = (float)a[k];
#pragma unroll
        for (int j = 0; j < 10; j++) acc[j] += s * W2[j * 1024 + k];
    }
#pragma unroll
    for (int j = 0; j < 10; j++)
#pragma unroll
        for (int off = 16; off; off >>= 1)
            acc[j] += __shfl_down_sync(0xffffffffu, acc[j], off);

    __shared__ float red[4][10];
    int w = tid >> 5, lm = tid & 31;
    if (lm == 0)
#pragma unroll
        for (int j = 0; j < 10; j++) red[w][j] = acc[j];
    __syncthreads();
    if (tid < 10) {
        float v = red[0][tid] + red[1][tid] + red[2][tid] + red[3][tid] + b2[tid];
        out[n * 10 + tid] = v;
    }
}

// ---------------------------------------------------------------------------
extern "C" void kernel_launch(void* const* d_in, const int* in_sizes, int n_in,
                              void* d_out, int out_size)
{
    const float* x    = (const float*)d_in[0];
    const float* w1dw = (const float*)d_in[1];
    const float* b1dw = (const float*)d_in[2];
    const float* w1pw = (const float*)d_in[3];
    const float* b1pw = (const float*)d_in[4];
    const float* w2dw = (const float*)d_in[5];
    const float* b2dw = (const float*)d_in[6];
    const float* w2pw = (const float*)d_in[7];
    const float* b2pw = (const float*)d_in[8];
    const float* fc1w = (const float*)d_in[9];
    const float* fc1b = (const float*)d_in[10];
    const float* fc2w = (const float*)d_in[11];
    const float* fc2b = (const float*)d_in[12];
    float* out = (float*)d_out;

    cudaFuncSetAttribute(k_conv2, cudaFuncAttributeMaxDynamicSharedMemorySize, C2_SMEM);
    const int SMEMG = 4 * ST_SZ;   // 196608
    cudaFuncSetAttribute(k_fc1imma, cudaFuncAttributeMaxDynamicSharedMemorySize, SMEMG);

    k_zero<<<1, 1>>>();
    k_wsplit<<<1024, 256>>>(fc1w);
    k_conv1<<<1024, 256>>>(x, w1dw, b1dw, w1pw, b1pw);
    k_conv2<<<1024, 256, C2_SMEM>>>(w2dw, b2dw, w2pw, b2pw);
    k_fc1imma<<<dim3(8, 8, 2), 256, SMEMG>>>();
    k_recflag<<<1024, 256>>>(fc1b);
    k_fix2<<<1024, 256>>>(fc1b);
    k_fix3<<<64, 256>>>(fc1w, fc1b);
    k_fc2<<<1024, 128>>>(fc2w, fc2b, out);
}

// round 15
// speedup vs baseline: 2.7415x; 1.0574x over previous
#include <cuda_runtime.h>
#include <cstdint>

// ---------------------------------------------------------------------------
// BinaryConnectNet forward (compute_103-safe: mma.sync/ldmatrix/cp.async).
//  conv1: dw3x3(g=3)+pw1x1(3->128), sign, maxpool2 -> a1 int8
//  conv2: dw dp4a + pw via s8 IMMA (pool+sign in-fragment) -> a2 int8
//  fc1:   2-plane int8-digit IMMA GEMM + int tier-1 bound + dp4a tier-2 +
//         tiny fp64 tier-3 (worklists), sign -> a3 int8
//  fc2:   a3 @ W2^T + b2 -> out [1024][10] fp32
// ---------------------------------------------------------------------------

__device__ int8_t g_a1[1024 * 256 * 128];
__device__ int8_t g_a2[1024 * 16384];
__device__ int8_t g_a3[1024 * 1024];
__device__ int8_t g_w1d[4ull * 1024 * 16384];   // [plane][j][k]
__device__ int    g_s32k[2ull * 1024 * 2048];   // [kslice][m][n']
__device__ int    g_R1[1024];                   // per-j tier1 bound (2^-32 units)
__device__ int    g_cnt,  g_cnt2;
__device__ int    g_list[1024 * 1024];
__device__ int    g_list2[1024 * 1024];

__device__ __forceinline__ float fsign(float v) {
    return (v > 0.f) ? 1.f : ((v < 0.f) ? -1.f : 0.f);
}
__device__ __forceinline__ int isign(int v) { return (v > 0) - (v < 0); }

__device__ __forceinline__ uint32_t smem_u32(const void* p) {
    uint32_t a;
    asm("{ .reg .u64 t; cvta.to.shared.u64 t, %1; cvt.u32.u64 %0, t; }"
        : "=r"(a) : "l"(p));
    return a;
}
__device__ __forceinline__ void cp16(uint32_t dst, const void* src) {
    asm volatile("cp.async.cg.shared.global [%0], [%1], 16;"
                 :: "r"(dst), "l"(src) : "memory");
}
__device__ __forceinline__ void ldsm4(uint32_t* r, uint32_t addr) {
    asm volatile("ldmatrix.sync.aligned.m8n8.x4.shared.b16 {%0,%1,%2,%3}, [%4];"
                 : "=r"(r[0]), "=r"(r[1]), "=r"(r[2]), "=r"(r[3]) : "r"(addr));
}
__device__ __forceinline__ void imma(int* c, const uint32_t* a,
                                     uint32_t b0, uint32_t b1) {
    asm volatile("mma.sync.aligned.m16n8k32.row.col.s32.s8.s8.s32 "
                 "{%0,%1,%2,%3}, {%4,%5,%6,%7}, {%8,%9}, {%0,%1,%2,%3};"
                 : "+r"(c[0]), "+r"(c[1]), "+r"(c[2]), "+r"(c[3])
                 : "r"(a[0]), "r"(a[1]), "r"(a[2]), "r"(a[3]),
                   "r"(b0), "r"(b1));
}

// ---------------------------------------------------------------------------
// Kernel 1: conv1 dw + pw + sign + maxpool, one image per block.
// ---------------------------------------------------------------------------
__global__ __launch_bounds__(256) void k_conv1(
    const float* __restrict__ x,
    const float* __restrict__ w1dw, const float* __restrict__ b1dw,
    const float* __restrict__ w1pw, const float* __restrict__ b1pw)
{
    __shared__ float sx[3][32][32];
    __shared__ float sdw[3][32][32];
    __shared__ float swdw[27];
    __shared__ float sbdw[3];
    __shared__ float swpw[128 * 3];
    __shared__ float sbpw[128];

    const int n = blockIdx.x, tid = threadIdx.x;

    for (int i = tid; i < 3072; i += 256) ((float*)sx)[i] = x[n * 3072 + i];
    if (tid < 27)  swdw[tid] = fsign(w1dw[tid]);
    if (tid < 3)   sbdw[tid] = fsign(b1dw[tid]);
    for (int i = tid; i < 384; i += 256) swpw[i] = fsign(w1pw[i]);
    if (tid < 128) sbpw[tid] = fsign(b1pw[tid]);
    __syncthreads();

    for (int i = tid; i < 3072; i += 256) {
        int c = i >> 10, p = i & 1023, y = p >> 5, xx = p & 31;
        float acc = 0.f;
#pragma unroll
        for (int ky = 0; ky < 3; ky++) {
#pragma unroll
            for (int kx = 0; kx < 3; kx++) {
                int yy = y + ky - 1, xw = xx + kx - 1;
                if (yy >= 0 && yy < 32 && xw >= 0 && xw < 32)
                    acc += swdw[c * 9 + ky * 3 + kx] * sx[c][yy][xw];
            }
        }
        acc += sbdw[c];
        ((float*)sdw)[i] = acc;
    }
    __syncthreads();

    for (int i = tid; i < 32768; i += 256) {
        int oc = i & 127, pp = i >> 7;
        int oy = pp >> 4, ox = pp & 15;
        float w0 = swpw[oc * 3 + 0], w1 = swpw[oc * 3 + 1],
              w2 = swpw[oc * 3 + 2], bb = sbpw[oc];
        float vmax = -1e30f;
#pragma unroll
        for (int d = 0; d < 4; d++) {
            int y = 2 * oy + (d >> 1), xw = 2 * ox + (d & 1);
            float v = w0 * sdw[0][y][xw] + w1 * sdw[1][y][xw]
                    + w2 * sdw[2][y][xw] + bb;
            vmax = fmaxf(vmax, v);
        }
        g_a1[n * 32768 + pp * 128 + oc] = (int8_t)(int)fsign(vmax);
    }
}

// ---------------------------------------------------------------------------
// Kernel 2: conv2.  dw via masked dp4a; pw via s8 mma.sync with pool+sign
// fused into the fragment epilogue.  One image per block, 2 blocks/SM.
// smem: [0,32768) a1-in / a2-out staging; [32768,65536) t (XOR-swizzled
// 128B rows); [65536,98304) pw weights (XOR-swizzled); then selectors+biases.
// ---------------------------------------------------------------------------
static constexpr int C2_SMEM = 103424;

__global__ void __launch_bounds__(256, 2) k_conv2(
    const float* __restrict__ w2dw, const float* __restrict__ b2dw,
    const float* __restrict__ w2pw, const float* __restrict__ b2pw)
{
    extern __shared__ char sm[];
    int8_t*   s_a1 = (int8_t*)sm;
    int8_t*   s_t  = (int8_t*)(sm + 32768);
    int8_t*   s_w  = (int8_t*)(sm + 65536);
    uint32_t* s_pk = (uint32_t*)(sm + 98304);
    int8_t*   s_bd = (int8_t*)(sm + 102912);
    int8_t*   s_bp = (int8_t*)(sm + 103040);

    const int n = blockIdx.x, tid = threadIdx.x;

    {
        const uint4* src = (const uint4*)(g_a1 + n * 32768);
        uint4* dst = (uint4*)s_a1;
        for (int i = tid; i < 2048; i += 256) dst[i] = src[i];
    }
    for (int i = tid; i < 1152; i += 256) {
        int c4 = i / 36, rem = i % 36, tap = rem >> 2, ch = rem & 3;
        int s = (int)fsign(w2dw[(c4 * 4 + ch) * 9 + tap]);
        s_pk[(c4 * 9 + tap) * 4 + ch] = ((uint32_t)(uint8_t)(char)s) << (8 * ch);
    }
    // pw weights into XOR-swizzled rows (row=oc, 128B of ic)
    for (int i = tid; i < 32768; i += 256) {
        int oc = i >> 7, cc = i & 127;
        uint32_t sw = oc * 128 + ((((cc >> 4) ^ (oc & 7)) << 4) | (cc & 15));
        s_w[sw] = (int8_t)(int)fsign(w2pw[i]);
    }
    if (tid < 128) s_bd[tid] = (int8_t)(int)fsign(b2dw[tid]);
    s_bp[tid] = (int8_t)(int)fsign(b2pw[tid]);
    __syncthreads();

    // depthwise 3x3 pad=1 (exact int, masked dp4a), swizzled store into s_t
    for (int i = tid; i < 8192; i += 256) {
        int c4 = i & 31, p = i >> 5, y = p >> 4, xx = p & 15;
        int a0 = (int)s_bd[c4 * 4 + 0], a1 = (int)s_bd[c4 * 4 + 1];
        int a2 = (int)s_bd[c4 * 4 + 2], a3 = (int)s_bd[c4 * 4 + 3];
        const uint32_t* pk = s_pk + c4 * 36;
#pragma unroll
        for (int ky = 0; ky < 3; ky++) {
#pragma unroll
            for (int kx = 0; kx < 3; kx++) {
                int yy = y + ky - 1, xw = xx + kx - 1;
                if (yy >= 0 && yy < 16 && xw >= 0 && xw < 16) {
                    int A = *(const int*)(s_a1 + (yy * 16 + xw) * 128 + c4 * 4);
                    const int tap = ky * 3 + kx;
                    a0 = __dp4a(A, (int)pk[tap * 4 + 0], a0);
                    a1 = __dp4a(A, (int)pk[tap * 4 + 1], a1);
                    a2 = __dp4a(A, (int)pk[tap * 4 + 2], a2);
                    a3 = __dp4a(A, (int)pk[tap * 4 + 3], a3);
                }
            }
        }
        int cc = c4 * 4;
        uint32_t sw = p * 128 + ((((cc >> 4) ^ (p & 7)) << 4) | (cc & 15));
        *(char4*)(s_t + sw) = make_char4((char)a0, (char)a1, (char)a2, (char)a3);
    }
    __syncthreads();

    // pointwise 128->256 via mma.sync; pool+bias+sign fused in epilogue.
    // 8 warps x (32 pos x 64 oc) tile, 4 oc-rounds.
    {
        const uint32_t smb = smem_u32(sm);
        const uint32_t tB = smb + 32768, wBs = smb + 65536;
        const int wid = tid >> 5, l = tid & 31;
        const int rowA = l & 15;
        const uint32_t cA = (uint32_t)(((l >> 4) << 4) ^ ((l & 7) << 4));
        const int rowB = (l & 7) + ((l >> 4) << 3);
        const uint32_t cB = (uint32_t)((((l >> 3) & 1) << 4) ^ ((l & 7) << 4));
        const uint32_t aBase = tB + (wid * 32 + rowA) * 128;
        const int gm = l >> 2, gn2 = (l & 3) << 1;
        int8_t* s_out = s_a1;   // a1 reads are done; reuse as a2 staging

        for (int r = 0; r < 4; r++) {
            const uint32_t bBase = wBs + (r * 64 + rowB) * 128;
            int c[2][8][4];
#pragma unroll
            for (int i = 0; i < 2; i++)
#pragma unroll
                for (int nn = 0; nn < 8; nn++)
#pragma unroll
                    for (int q = 0; q < 4; q++) c[i][nn][q] = 0;

#pragma unroll
            for (int kk = 0; kk < 4; kk++) {
                const uint32_t ka = ((uint32_t)(kk << 5)) ^ cA;
                const uint32_t kb = ((uint32_t)(kk << 5)) ^ cB;
                uint32_t a[2][4], b[4][4];
                ldsm4(a[0], aBase + 0 * 2048 + ka);
                ldsm4(a[1], aBase + 1 * 2048 + ka);
#pragma unroll
                for (int t = 0; t < 4; t++)
                    ldsm4(b[t], bBase + t * 2048 + kb);
#pragma unroll
                for (int i = 0; i < 2; i++)
#pragma unroll
                    for (int t = 0; t < 4; t++) {
                        imma(c[i][2 * t],     a[i], b[t][0], b[t][1]);
                        imma(c[i][2 * t + 1], a[i], b[t][2], b[t][3]);
                    }
            }

            // pool(2x2) + bias + sign.  y-pair = (i=0,i=1) same lane;
            // x-pair = shfl.bfly(4); rows gm / gm+8 give qx and qx+4.
#pragma unroll
            for (int nn = 0; nn < 8; nn++) {
                int m0 = max(c[0][nn][0], c[1][nn][0]);
                int m1 = max(c[0][nn][1], c[1][nn][1]);
                int m2 = max(c[0][nn][2], c[1][nn][2]);
                int m3 = max(c[0][nn][3], c[1][nn][3]);
                m0 = max(m0, __shfl_xor_sync(0xffffffffu, m0, 4));
                m1 = max(m1, __shfl_xor_sync(0xffffffffu, m1, 4));
                m2 = max(m2, __shfl_xor_sync(0xffffffffu, m2, 4));
                m3 = max(m3, __shfl_xor_sync(0xffffffffu, m3, 4));
                if ((l & 4) == 0) {
                    int oc0 = r * 64 + nn * 8 + gn2;
                    int b0 = (int)s_bp[oc0], b1 = (int)s_bp[oc0 + 1];
                    int qx = gm >> 1;
                    s_out[oc0 * 64 + wid * 8 + qx]           = (int8_t)isign(m0 + b0);
                    s_out[(oc0 + 1) * 64 + wid * 8 + qx]     = (int8_t)isign(m1 + b1);
                    s_out[oc0 * 64 + wid * 8 + qx + 4]       = (int8_t)isign(m2 + b0);
                    s_out[(oc0 + 1) * 64 + wid * 8 + qx + 4] = (int8_t)isign(m3 + b1);
                }
            }
        }
    }
    __syncthreads();

    {
        uint4* g = (uint4*)(g_a2 + n * 16384);
        const uint4* s2 = (const uint4*)s_a1;
        for (int i = tid; i < 1024; i += 256) g[i] = s2[i];
    }
}

// ---------------------------------------------------------------------------
// Kernel W: 4 digit planes + int residual bound (no fp64); zeroes counters.
// ---------------------------------------------------------------------------
__global__ __launch_bounds__(256) void k_wsplit(const float* __restrict__ W)
{
    __shared__ int rs[256];
    const int j = blockIdx.x, tid = threadIdx.x;
    if (j == 0 && tid == 0) { g_cnt = 0; g_cnt2 = 0; }
    const float4* W4 = (const float4*)(W + (size_t)j * 16384);
    char4* P0 = (char4*)(g_w1d + 0ull * 16777216 + (size_t)j * 16384);
    char4* P1 = (char4*)(g_w1d + 1ull * 16777216 + (size_t)j * 16384);
    char4* P2 = (char4*)(g_w1d + 2ull * 16777216 + (size_t)j * 16384);
    char4* P3 = (char4*)(g_w1d + 3ull * 16777216 + (size_t)j * 16384);

    int racc = 0;
#pragma unroll 4
    for (int it = 0; it < 16; it++) {
        const int k4 = tid + (it << 8);
        float4 w = W4[k4];
        float wv[4] = {w.x, w.y, w.z, w.w};
        char dd0[4], dd1[4], dd2[4], dd3[4];
#pragma unroll
        for (int c = 0; c < 4; c++) {
            int n18 = __float2int_rn(wv[c] * 262144.0f);
            n18 = max(-16256, min(16256, n18));
            int d0 = (n18 + 64) >> 7;
            int d1 = n18 - (d0 << 7);
            int w32 = __float2int_rn(wv[c] * 4294967296.0f);
            int r32 = w32 - (n18 << 14);
            int d2 = (r32 + 64) >> 7;
            d2 = max(-127, min(127, d2));
            int d3 = r32 - (d2 << 7);
            d3 = max(-127, min(127, d3));
            racc += abs(r32);
            dd0[c] = (char)d0; dd1[c] = (char)d1;
            dd2[c] = (char)d2; dd3[c] = (char)d3;
        }
        P0[k4] = make_char4(dd0[0], dd0[1], dd0[2], dd0[3]);
        P1[k4] = make_char4(dd1[0], dd1[1], dd1[2], dd1[3]);
        P2[k4] = make_char4(dd2[0], dd2[1], dd2[2], dd2[3]);
        P3[k4] = make_char4(dd3[0], dd3[1], dd3[2], dd3[3]);
    }
    rs[tid] = racc;
    __syncthreads();
    for (int s = 128; s; s >>= 1) {
        if (tid < s) rs[tid] += rs[tid + s];
        __syncthreads();
    }
    if (tid == 0) g_R1[j] = rs[0] + 8192 + 4;
}

// ---------------------------------------------------------------------------
// Kernel 3: fc1 IMMA GEMM on planes 0,1.  Split-K, R10-proven tile shape.
// Grid (8 n-tiles, 8 m-tiles, 2 kslices).  CTA 128m x 256n, 64 its of BK=128.
// ---------------------------------------------------------------------------
static constexpr int ST_A  = 16384;
static constexpr int ST_SZ = 49152;

__device__ __forceinline__ void gemm_load_stage(
    uint32_t stage, const int8_t* Ag, const int8_t* Bg, int kt, int tid)
{
    const int k0 = kt << 7;
#pragma unroll
    for (int r = 0; r < 4; r++) {
        int c = tid + (r << 8);
        int row = c >> 3, seg = (c & 7) << 4;
        uint32_t dst = stage + row * 128 + (seg ^ ((row & 7) << 4));
        cp16(dst, Ag + (size_t)row * 16384 + k0 + seg);
    }
#pragma unroll
    for (int r = 0; r < 8; r++) {
        int c = tid + (r << 8);
        int row = c >> 3, seg = (c & 7) << 4;
        uint32_t dst = stage + ST_A + row * 128 + (seg ^ ((row & 7) << 4));
        cp16(dst, Bg + (size_t)row * 16384 + k0 + seg);
    }
}

__global__ __launch_bounds__(256, 1) void k_fc1imma()
{
    extern __shared__ char sm[];
    const uint32_t smb = smem_u32(sm);

    const int tid = threadIdx.x, wid = tid >> 5, l = tid & 31;
    const int n0 = blockIdx.x * 256, m0 = blockIdx.y * 128;
    const int ks = blockIdx.z;
    const int warp_m = wid & 1, warp_n = wid >> 1;

    const int8_t* Ag = g_a2  + (size_t)m0 * 16384 + (size_t)ks * 8192;
    const int8_t* Bg = g_w1d + (size_t)n0 * 16384 + (size_t)ks * 8192;

    const int rowA = l & 15;
    const uint32_t cA = (uint32_t)(((l >> 4) << 4) ^ ((l & 7) << 4));
    const int rowB = (l & 7) + ((l >> 4) << 3);
    const uint32_t cB = (uint32_t)((((l >> 3) & 1) << 4) ^ ((l & 7) << 4));
    const uint32_t aBase = (uint32_t)((warp_m * 64 + rowA) * 128);
    const uint32_t bBase = (uint32_t)(ST_A + (warp_n * 64 + rowB) * 128);

    int c[4][8][4];
#pragma unroll
    for (int i = 0; i < 4; i++)
#pragma unroll
        for (int nn = 0; nn < 8; nn++)
#pragma unroll
            for (int q = 0; q < 4; q++) c[i][nn][q] = 0;

    gemm_load_stage(smb + 0 * ST_SZ, Ag, Bg, 0, tid);
    asm volatile("cp.async.commit_group;" ::: "memory");
    gemm_load_stage(smb + 1 * ST_SZ, Ag, Bg, 1, tid);
    asm volatile("cp.async.commit_group;" ::: "memory");
    gemm_load_stage(smb + 2 * ST_SZ, Ag, Bg, 2, tid);
    asm volatile("cp.async.commit_group;" ::: "memory");

    for (int it = 0; it < 64; it++) {
        asm volatile("cp.async.wait_group 2;" ::: "memory");
        __syncthreads();
        if (it + 3 < 64)
            gemm_load_stage(smb + ((it + 3) & 3) * ST_SZ, Ag, Bg, it + 3, tid);
        asm volatile("cp.async.commit_group;" ::: "memory");

        const uint32_t buf = smb + (it & 3) * ST_SZ;
#pragma unroll
        for (int kk = 0; kk < 4; kk++) {
            const uint32_t ka = ((uint32_t)(kk << 5)) ^ cA;
            const uint32_t kb = ((uint32_t)(kk << 5)) ^ cB;
            uint32_t a[4][4], b[4][4];
#pragma unroll
            for (int i = 0; i < 4; i++)
                ldsm4(a[i], buf + aBase + i * 2048 + ka);
#pragma unroll
            for (int t = 0; t < 4; t++)
                ldsm4(b[t], buf + bBase + t * 2048 + kb);
#pragma unroll
            for (int i = 0; i < 4; i++)
#pragma unroll
                for (int t = 0; t < 4; t++) {
                    imma(c[i][2 * t],     a[i], b[t][0], b[t][1]);
                    imma(c[i][2 * t + 1], a[i], b[t][2], b[t][3]);
                }
        }
    }
    __syncthreads();

    int* so = (int*)sm;
    const int gm = l >> 2, gn = (l & 3) << 1;
#pragma unroll
    for (int i = 0; i < 4; i++) {
        int ml = warp_m * 64 + i * 16 + gm;
#pragma unroll
        for (int nn = 0; nn < 8; nn++) {
            int nl = warp_n * 64 + nn * 8 + gn;
            so[ml * 260 + nl]           = c[i][nn][0];
            so[ml * 260 + nl + 1]       = c[i][nn][1];
            so[(ml + 8) * 260 + nl]     = c[i][nn][2];
            so[(ml + 8) * 260 + nl + 1] = c[i][nn][3];
        }
    }
    __syncthreads();
    {
        int* gp = g_s32k + (size_t)ks * 2097152 + (size_t)m0 * 2048 + n0;
        for (int i = tid; i < 32768; i += 256) {
            int ml = i >> 8, nl = i & 255;
            gp[(size_t)ml * 2048 + nl] = so[ml * 260 + nl];
        }
    }
}

// ---------------------------------------------------------------------------
// Kernel 3b: tier-1.  V = S01*2^14 + B32 (int64).  |V| > R1_j -> sign.
// Else push to worklist.  One block per m.
// ---------------------------------------------------------------------------
__global__ __launch_bounds__(256) void k_recflag(const float* __restrict__ bf)
{
    __shared__ int s_cnt, s_base;
    __shared__ int s_list[1024];

    const int m = blockIdx.x, t = threadIdx.x;
    if (t == 0) s_cnt = 0;
    __syncthreads();

    const int* b0 = g_s32k + (size_t)m * 2048;
    const int* b1 = g_s32k + 2097152ull + (size_t)m * 2048;
    const int4 h0 = ((const int4*)b0)[t];
    const int4 h1 = ((const int4*)(b0 + 1024))[t];
    const int4 g0 = ((const int4*)b1)[t];
    const int4 g1 = ((const int4*)(b1 + 1024))[t];
    const float4 bb = ((const float4*)bf)[t];
    const int4 Rr = ((const int4*)g_R1)[t];

    int sv[4] = {h0.x + g0.x, h0.y + g0.y, h0.z + g0.z, h0.w + g0.w};
    int lv[4] = {h1.x + g1.x, h1.y + g1.y, h1.z + g1.z, h1.w + g1.w};
    float bv[4] = {bb.x, bb.y, bb.z, bb.w};
    int Rv[4] = {Rr.x, Rr.y, Rr.z, Rr.w};

    char o[4] = {0, 0, 0, 0};
#pragma unroll
    for (int cix = 0; cix < 4; cix++) {
        long long S01 = ((long long)sv[cix] << 7) + lv[cix];
        long long B32 = __float2ll_rn(bv[cix] * 4294967296.0f);
        long long V = (S01 << 14) + B32;
        long long aV = (V < 0) ? -V : V;
        if (aV > (long long)Rv[cix]) {
            o[cix] = (char)((V > 0) ? 1 : -1);
        } else {
            int p = atomicAdd(&s_cnt, 1);
            s_list[p] = m * 1024 + t * 4 + cix;
        }
    }
    ((char4*)g_a3)[m * 256 + t] = make_char4(o[0], o[1], o[2], o[3]);
    __syncthreads();

    if (t == 0 && s_cnt > 0) s_base = atomicAdd(&g_cnt, s_cnt);
    __syncthreads();
    for (int i = t; i < s_cnt; i += 256) g_list[s_base + i] = s_list[i];
}

// ---------------------------------------------------------------------------
// Kernel 3c: tier-2.  One warp per entry; dp4a on planes 2,3 (exact).
// ---------------------------------------------------------------------------
__global__ __launch_bounds__(256) void k_fix2(const float* __restrict__ bf)
{
    const int tid = threadIdx.x, lane = tid & 31, w = tid >> 5;
    const int gw = blockIdx.x * 8 + w, stride = gridDim.x * 8;
    const int cnt = g_cnt;

    for (int e = gw; e < cnt; e += stride) {
        const int pair = g_list[e];
        const int m = pair >> 10, j = pair & 1023;
        const int* aw = (const int*)(g_a2 + (size_t)m * 16384);
        const int* p2 = (const int*)(g_w1d + 2ull * 16777216 + (size_t)j * 16384);
        const int* p3 = (const int*)(g_w1d + 3ull * 16777216 + (size_t)j * 16384);

        int s2 = 0, s3 = 0;
#pragma unroll 4
        for (int c = lane; c < 4096; c += 32) {
            int av = aw[c];
            s2 = __dp4a(p2[c], av, s2);
            s3 = __dp4a(p3[c], av, s3);
        }
#pragma unroll
        for (int off = 16; off; off >>= 1) {
            s2 += __shfl_xor_sync(0xffffffffu, s2, off);
            s3 += __shfl_xor_sync(0xffffffffu, s3, off);
        }
        if (lane == 0) {
            int S0 = g_s32k[(size_t)m * 2048 + j]
                   + g_s32k[2097152ull + (size_t)m * 2048 + j];
            int S1 = g_s32k[(size_t)m * 2048 + 1024 + j]
                   + g_s32k[2097152ull + (size_t)m * 2048 + 1024 + j];
            long long S01 = ((long long)S0 << 7) + S1;
            long long B32 = __float2ll_rn(bf[j] * 4294967296.0f);
            long long T = (S01 << 14) + (long long)s2 * 128 + s3 + B32;
            long long aT = (T < 0) ? -T : T;
            if (aT > 8196) {
                g_a3[(size_t)m * 1024 + j] = (char)((T > 0) ? 1 : -1);
            } else {
                int p = atomicAdd(&g_cnt2, 1);
                g_list2[p] = pair;
            }
        }
    }
}

// ---------------------------------------------------------------------------
// Kernel 3d: tier-3.  fp64 dot with true fp32 weights (expected ~0-8 entries).
// ---------------------------------------------------------------------------
__global__ __launch_bounds__(256) void k_fix3(
    const float* __restrict__ W, const float* __restrict__ bf)
{
    __shared__ double rs[256];
    const int t = threadIdx.x;
    const int cnt = g_cnt2;

    for (int e = blockIdx.x; e < cnt; e += gridDim.x) {
        const int pair = g_list2[e];
        const int m = pair >> 10, j = pair & 1023;
        const float* wr = W + (size_t)j * 16384;
        const int8_t* ar = g_a2 + (size_t)m * 16384;

        double a0 = 0.0, a1 = 0.0, a2 = 0.0, a3 = 0.0;
        for (int k = t; k < 16384; k += 1024) {
            a0 += (double)wr[k]       * (double)ar[k];
            a1 += (double)wr[k + 256] * (double)ar[k + 256];
            a2 += (double)wr[k + 512] * (double)ar[k + 512];
            a3 += (double)wr[k + 768] * (double)ar[k + 768];
        }
        rs[t] = (a0 + a1) + (a2 + a3);
        __syncthreads();
        for (int s = 128; s; s >>= 1) {
            if (t < s) rs[t] += rs[t + s];
            __syncthreads();
        }
        if (t == 0) {
            double v = rs[0] + (double)bf[j];
            g_a3[(size_t)m * 1024 + j] =
                (char)((v > 0.0) ? 1 : ((v < 0.0) ? -1 : 0));
        }
        __syncthreads();
    }
}

// ---------------------------------------------------------------------------
// Kernel 4: fc2  out[1024][10] = a3 @ W2^T + b2
// ---------------------------------------------------------------------------
__global__ __launch_bounds__(128) void k_fc2(
    const float* __restrict__ W2, const float* __restrict__ b2,
    float* __restrict__ out)
{
    const int n = blockIdx.x, tid = threadIdx.x;
    float acc[10] = {};
    const int8_t* a = g_a3 + n * 1024;
    for (int k = tid; k < 1024; k += 128) {
        float s = (float)a[k];
#pragma unroll
        for (int j = 0; j < 10; j++) acc[j] += s * W2[j * 1024 + k];
    }
#pragma unroll
    for (int j = 0; j < 10; j++)
#pragma unroll
        for (int off = 16; off; off >>= 1)
            acc[j] += __shfl_down_sync(0xffffffffu, acc[j], off);

    __shared__ float red[4][10];
    int w = tid >> 5, lm = tid & 31;
    if (lm == 0)
#pragma unroll
        for (int j = 0; j < 10; j++) red[w][j] = acc[j];
    __syncthreads();
    if (tid < 10) {
        float v = red[0][tid] + red[1][tid] + red[2][tid] + red[3][tid] + b2[tid];
        out[n * 10 + tid] = v;
    }
}

// ---------------------------------------------------------------------------
extern "C" void kernel_launch(void* const* d_in, const int* in_sizes, int n_in,
                              void* d_out, int out_size)
{
    const float* x    = (const float*)d_in[0];
    const float* w1dw = (const float*)d_in[1];
    const float* b1dw = (const float*)d_in[2];
    const float* w1pw = (const float*)d_in[3];
    const float* b1pw = (const float*)d_in[4];
    const float* w2dw = (const float*)d_in[5];
    const float* b2dw = (const float*)d_in[6];
    const float* w2pw = (const float*)d_in[7];
    const float* b2pw = (const float*)d_in[8];
    const float* fc1w = (const float*)d_in[9];
    const float* fc1b = (const float*)d_in[10];
    const float* fc2w = (const float*)d_in[11];
    const float* fc2b = (const float*)d_in[12];
    float* out = (float*)d_out;

    cudaFuncSetAttribute(k_conv2, cudaFuncAttributeMaxDynamicSharedMemorySize, C2_SMEM);
    const int SMEMG = 4 * ST_SZ;   // 196608
    cudaFuncSetAttribute(k_fc1imma, cudaFuncAttributeMaxDynamicSharedMemorySize, SMEMG);

    k_wsplit<<<1024, 256>>>(fc1w);
    k_conv1<<<1024, 256>>>(x, w1dw, b1dw, w1pw, b1pw);
    k_conv2<<<1024, 256, C2_SMEM>>>(w2dw, b2dw, w2pw, b2pw);
    k_fc1imma<<<dim3(8, 8, 2), 256, SMEMG>>>();
    k_recflag<<<1024, 256>>>(fc1b);
    k_fix2<<<1024, 256>>>(fc1b);
    k_fix3<<<64, 256>>>(fc1w, fc1b);
    k_fc2<<<1024, 128>>>(fc2w, fc2b, out);
}

// round 16
// speedup vs baseline: 2.9318x; 1.0694x over previous
#include <cuda_runtime.h>
#include <cstdint>

// ---------------------------------------------------------------------------
// BinaryConnectNet forward (compute_103-safe: mma.sync/ldmatrix/cp.async).
//  conv1: dw3x3(g=3)+pw1x1(3->128), sign, maxpool2 -> a1 int8
//  conv2: dw dp4a + pw via s8 IMMA (pool+sign in-fragment) -> a2 int8
//  fc1:   2-plane int8-digit IMMA GEMM, PERSISTENT 148-CTA grid with
//         flexible K-partitioning + exact s32 atomicAdd accumulation;
//         int tier-1 bound + dp4a tier-2 + tiny fp64 tier-3. sign -> a3.
//  fc2:   a3 @ W2^T + b2 -> out [1024][10] fp32
// ---------------------------------------------------------------------------

__device__ int8_t g_a1[1024 * 256 * 128];
__device__ int8_t g_a2[1024 * 16384];
__device__ int8_t g_a3[1024 * 1024];
__device__ int8_t g_w1d[4ull * 1024 * 16384];   // [plane][j][k]
__device__ int    g_s32[1024ull * 2048];        // [m][n'] combined accumulator
__device__ int    g_R1[1024];                   // per-j tier1 bound (2^-32 units)
__device__ int    g_cnt,  g_cnt2;
__device__ int    g_list[1024 * 1024];
__device__ int    g_list2[1024 * 1024];

__device__ __forceinline__ float fsign(float v) {
    return (v > 0.f) ? 1.f : ((v < 0.f) ? -1.f : 0.f);
}
__device__ __forceinline__ int isign(int v) { return (v > 0) - (v < 0); }

__device__ __forceinline__ uint32_t smem_u32(const void* p) {
    uint32_t a;
    asm("{ .reg .u64 t; cvta.to.shared.u64 t, %1; cvt.u32.u64 %0, t; }"
        : "=r"(a) : "l"(p));
    return a;
}
__device__ __forceinline__ void cp16(uint32_t dst, const void* src) {
    asm volatile("cp.async.cg.shared.global [%0], [%1], 16;"
                 :: "r"(dst), "l"(src) : "memory");
}
__device__ __forceinline__ void ldsm4(uint32_t* r, uint32_t addr) {
    asm volatile("ldmatrix.sync.aligned.m8n8.x4.shared.b16 {%0,%1,%2,%3}, [%4];"
                 : "=r"(r[0]), "=r"(r[1]), "=r"(r[2]), "=r"(r[3]) : "r"(addr));
}
__device__ __forceinline__ void imma(int* c, const uint32_t* a,
                                     uint32_t b0, uint32_t b1) {
    asm volatile("mma.sync.aligned.m16n8k32.row.col.s32.s8.s8.s32 "
                 "{%0,%1,%2,%3}, {%4,%5,%6,%7}, {%8,%9}, {%0,%1,%2,%3};"
                 : "+r"(c[0]), "+r"(c[1]), "+r"(c[2]), "+r"(c[3])
                 : "r"(a[0]), "r"(a[1]), "r"(a[2]), "r"(a[3]),
                   "r"(b0), "r"(b1));
}

// ---------------------------------------------------------------------------
// Kernel Z: zero the s32 accumulator (8MB) + worklist counters.
// ---------------------------------------------------------------------------
__global__ __launch_bounds__(256) void k_zs()
{
    const size_t i = (size_t)blockIdx.x * 256 + threadIdx.x;
    ((int4*)g_s32)[i] = make_int4(0, 0, 0, 0);
    if (i == 0) { g_cnt = 0; g_cnt2 = 0; }
}

// ---------------------------------------------------------------------------
// Kernel 1: conv1 dw + pw + sign + maxpool, one image per block.
// ---------------------------------------------------------------------------
__global__ __launch_bounds__(256) void k_conv1(
    const float* __restrict__ x,
    const float* __restrict__ w1dw, const float* __restrict__ b1dw,
    const float* __restrict__ w1pw, const float* __restrict__ b1pw)
{
    __shared__ float sx[3][32][32];
    __shared__ float sdw[3][32][32];
    __shared__ float swdw[27];
    __shared__ float sbdw[3];
    __shared__ float swpw[128 * 3];
    __shared__ float sbpw[128];

    const int n = blockIdx.x, tid = threadIdx.x;

    for (int i = tid; i < 3072; i += 256) ((float*)sx)[i] = x[n * 3072 + i];
    if (tid < 27)  swdw[tid] = fsign(w1dw[tid]);
    if (tid < 3)   sbdw[tid] = fsign(b1dw[tid]);
    for (int i = tid; i < 384; i += 256) swpw[i] = fsign(w1pw[i]);
    if (tid < 128) sbpw[tid] = fsign(b1pw[tid]);
    __syncthreads();

    for (int i = tid; i < 3072; i += 256) {
        int c = i >> 10, p = i & 1023, y = p >> 5, xx = p & 31;
        float acc = 0.f;
#pragma unroll
        for (int ky = 0; ky < 3; ky++) {
#pragma unroll
            for (int kx = 0; kx < 3; kx++) {
                int yy = y + ky - 1, xw = xx + kx - 1;
                if (yy >= 0 && yy < 32 && xw >= 0 && xw < 32)
                    acc += swdw[c * 9 + ky * 3 + kx] * sx[c][yy][xw];
            }
        }
        acc += sbdw[c];
        ((float*)sdw)[i] = acc;
    }
    __syncthreads();

    for (int i = tid; i < 32768; i += 256) {
        int oc = i & 127, pp = i >> 7;
        int oy = pp >> 4, ox = pp & 15;
        float w0 = swpw[oc * 3 + 0], w1 = swpw[oc * 3 + 1],
              w2 = swpw[oc * 3 + 2], bb = sbpw[oc];
        float vmax = -1e30f;
#pragma unroll
        for (int d = 0; d < 4; d++) {
            int y = 2 * oy + (d >> 1), xw = 2 * ox + (d & 1);
            float v = w0 * sdw[0][y][xw] + w1 * sdw[1][y][xw]
                    + w2 * sdw[2][y][xw] + bb;
            vmax = fmaxf(vmax, v);
        }
        g_a1[n * 32768 + pp * 128 + oc] = (int8_t)(int)fsign(vmax);
    }
}

// ---------------------------------------------------------------------------
// Kernel 2: conv2.  dw via masked dp4a; pw via s8 mma.sync with pool+sign
// fused into the fragment epilogue.  One image per block, 2 blocks/SM.
// ---------------------------------------------------------------------------
static constexpr int C2_SMEM = 103424;

__global__ void __launch_bounds__(256, 2) k_conv2(
    const float* __restrict__ w2dw, const float* __restrict__ b2dw,
    const float* __restrict__ w2pw, const float* __restrict__ b2pw)
{
    extern __shared__ char sm[];
    int8_t*   s_a1 = (int8_t*)sm;
    int8_t*   s_t  = (int8_t*)(sm + 32768);
    int8_t*   s_w  = (int8_t*)(sm + 65536);
    uint32_t* s_pk = (uint32_t*)(sm + 98304);
    int8_t*   s_bd = (int8_t*)(sm + 102912);
    int8_t*   s_bp = (int8_t*)(sm + 103040);

    const int n = blockIdx.x, tid = threadIdx.x;

    {
        const uint4* src = (const uint4*)(g_a1 + n * 32768);
        uint4* dst = (uint4*)s_a1;
        for (int i = tid; i < 2048; i += 256) dst[i] = src[i];
    }
    for (int i = tid; i < 1152; i += 256) {
        int c4 = i / 36, rem = i % 36, tap = rem >> 2, ch = rem & 3;
        int s = (int)fsign(w2dw[(c4 * 4 + ch) * 9 + tap]);
        s_pk[(c4 * 9 + tap) * 4 + ch] = ((uint32_t)(uint8_t)(char)s) << (8 * ch);
    }
    for (int i = tid; i < 32768; i += 256) {
        int oc = i >> 7, cc = i & 127;
        uint32_t sw = oc * 128 + ((((cc >> 4) ^ (oc & 7)) << 4) | (cc & 15));
        s_w[sw] = (int8_t)(int)fsign(w2pw[i]);
    }
    if (tid < 128) s_bd[tid] = (int8_t)(int)fsign(b2dw[tid]);
    s_bp[tid] = (int8_t)(int)fsign(b2pw[tid]);
    __syncthreads();

    for (int i = tid; i < 8192; i += 256) {
        int c4 = i & 31, p = i >> 5, y = p >> 4, xx = p & 15;
        int a0 = (int)s_bd[c4 * 4 + 0], a1 = (int)s_bd[c4 * 4 + 1];
        int a2 = (int)s_bd[c4 * 4 + 2], a3 = (int)s_bd[c4 * 4 + 3];
        const uint32_t* pk = s_pk + c4 * 36;
#pragma unroll
        for (int ky = 0; ky < 3; ky++) {
#pragma unroll
            for (int kx = 0; kx < 3; kx++) {
                int yy = y + ky - 1, xw = xx + kx - 1;
                if (yy >= 0 && yy < 16 && xw >= 0 && xw < 16) {
                    int A = *(const int*)(s_a1 + (yy * 16 + xw) * 128 + c4 * 4);
                    const int tap = ky * 3 + kx;
                    a0 = __dp4a(A, (int)pk[tap * 4 + 0], a0);
                    a1 = __dp4a(A, (int)pk[tap * 4 + 1], a1);
                    a2 = __dp4a(A, (int)pk[tap * 4 + 2], a2);
                    a3 = __dp4a(A, (int)pk[tap * 4 + 3], a3);
                }
            }
        }
        int cc = c4 * 4;
        uint32_t sw = p * 128 + ((((cc >> 4) ^ (p & 7)) << 4) | (cc & 15));
        *(char4*)(s_t + sw) = make_char4((char)a0, (char)a1, (char)a2, (char)a3);
    }
    __syncthreads();

    {
        const uint32_t smb = smem_u32(sm);
        const uint32_t tB = smb + 32768, wBs = smb + 65536;
        const int wid = tid >> 5, l = tid & 31;
        const int rowA = l & 15;
        const uint32_t cA = (uint32_t)(((l >> 4) << 4) ^ ((l & 7) << 4));
        const int rowB = (l & 7) + ((l >> 4) << 3);
        const uint32_t cB = (uint32_t)((((l >> 3) & 1) << 4) ^ ((l & 7) << 4));
        const uint32_t aBase = tB + (wid * 32 + rowA) * 128;
        const int gm = l >> 2, gn2 = (l & 3) << 1;
        int8_t* s_out = s_a1;

        for (int r = 0; r < 4; r++) {
            const uint32_t bBase = wBs + (r * 64 + rowB) * 128;
            int c[2][8][4];
#pragma unroll
            for (int i = 0; i < 2; i++)
#pragma unroll
                for (int nn = 0; nn < 8; nn++)
#pragma unroll
                    for (int q = 0; q < 4; q++) c[i][nn][q] = 0;

#pragma unroll
            for (int kk = 0; kk < 4; kk++) {
                const uint32_t ka = ((uint32_t)(kk << 5)) ^ cA;
                const uint32_t kb = ((uint32_t)(kk << 5)) ^ cB;
                uint32_t a[2][4], b[4][4];
                ldsm4(a[0], aBase + 0 * 2048 + ka);
                ldsm4(a[1], aBase + 1 * 2048 + ka);
#pragma unroll
                for (int t = 0; t < 4; t++)
                    ldsm4(b[t], bBase + t * 2048 + kb);
#pragma unroll
                for (int i = 0; i < 2; i++)
#pragma unroll
                    for (int t = 0; t < 4; t++) {
                        imma(c[i][2 * t],     a[i], b[t][0], b[t][1]);
                        imma(c[i][2 * t + 1], a[i], b[t][2], b[t][3]);
                    }
            }

#pragma unroll
            for (int nn = 0; nn < 8; nn++) {
                int m0 = max(c[0][nn][0], c[1][nn][0]);
                int m1 = max(c[0][nn][1], c[1][nn][1]);
                int m2 = max(c[0][nn][2], c[1][nn][2]);
                int m3 = max(c[0][nn][3], c[1][nn][3]);
                m0 = max(m0, __shfl_xor_sync(0xffffffffu, m0, 4));
                m1 = max(m1, __shfl_xor_sync(0xffffffffu, m1, 4));
                m2 = max(m2, __shfl_xor_sync(0xffffffffu, m2, 4));
                m3 = max(m3, __shfl_xor_sync(0xffffffffu, m3, 4));
                if ((l & 4) == 0) {
                    int oc0 = r * 64 + nn * 8 + gn2;
                    int b0 = (int)s_bp[oc0], b1 = (int)s_bp[oc0 + 1];
                    int qx = gm >> 1;
                    s_out[oc0 * 64 + wid * 8 + qx]           = (int8_t)isign(m0 + b0);
                    s_out[(oc0 + 1) * 64 + wid * 8 + qx]     = (int8_t)isign(m1 + b1);
                    s_out[oc0 * 64 + wid * 8 + qx + 4]       = (int8_t)isign(m2 + b0);
                    s_out[(oc0 + 1) * 64 + wid * 8 + qx + 4] = (int8_t)isign(m3 + b1);
                }
            }
        }
    }
    __syncthreads();

    {
        uint4* g = (uint4*)(g_a2 + n * 16384);
        const uint4* s2 = (const uint4*)s_a1;
        for (int i = tid; i < 1024; i += 256) g[i] = s2[i];
    }
}

// ---------------------------------------------------------------------------
// Kernel W: 4 digit planes + int residual bound (no fp64).
// ---------------------------------------------------------------------------
__global__ __launch_bounds__(256) void k_wsplit(const float* __restrict__ W)
{
    __shared__ int rs[256];
    const int j = blockIdx.x, tid = threadIdx.x;
    const float4* W4 = (const float4*)(W + (size_t)j * 16384);
    char4* P0 = (char4*)(g_w1d + 0ull * 16777216 + (size_t)j * 16384);
    char4* P1 = (char4*)(g_w1d + 1ull * 16777216 + (size_t)j * 16384);
    char4* P2 = (char4*)(g_w1d + 2ull * 16777216 + (size_t)j * 16384);
    char4* P3 = (char4*)(g_w1d + 3ull * 16777216 + (size_t)j * 16384);

    int racc = 0;
#pragma unroll 4
    for (int it = 0; it < 16; it++) {
        const int k4 = tid + (it << 8);
        float4 w = W4[k4];
        float wv[4] = {w.x, w.y, w.z, w.w};
        char dd0[4], dd1[4], dd2[4], dd3[4];
#pragma unroll
        for (int c = 0; c < 4; c++) {
            int n18 = __float2int_rn(wv[c] * 262144.0f);
            n18 = max(-16256, min(16256, n18));
            int d0 = (n18 + 64) >> 7;
            int d1 = n18 - (d0 << 7);
            int w32 = __float2int_rn(wv[c] * 4294967296.0f);
            int r32 = w32 - (n18 << 14);
            int d2 = (r32 + 64) >> 7;
            d2 = max(-127, min(127, d2));
            int d3 = r32 - (d2 << 7);
            d3 = max(-127, min(127, d3));
            racc += abs(r32);
            dd0[c] = (char)d0; dd1[c] = (char)d1;
            dd2[c] = (char)d2; dd3[c] = (char)d3;
        }
        P0[k4] = make_char4(dd0[0], dd0[1], dd0[2], dd0[3]);
        P1[k4] = make_char4(dd1[0], dd1[1], dd1[2], dd1[3]);
        P2[k4] = make_char4(dd2[0], dd2[1], dd2[2], dd2[3]);
        P3[k4] = make_char4(dd3[0], dd3[1], dd3[2], dd3[3]);
    }
    rs[tid] = racc;
    __syncthreads();
    for (int s = 128; s; s >>= 1) {
        if (tid < s) rs[tid] += rs[tid + s];
        __syncthreads();
    }
    if (tid == 0) g_R1[j] = rs[0] + 8192 + 4;
}

// ---------------------------------------------------------------------------
// Kernel 3: fc1 IMMA GEMM, PERSISTENT.  Grid = 148 CTAs.
// Work = 64 spatial tiles (8m x 8n of 128x256) x 128 K-its = 8192 units.
// CTA r owns units [r*8192/148, (r+1)*8192/148): zero frags per tile
// segment, 4-stage cp.async pipeline, atomicAdd s32 epilogue (exact).
// ---------------------------------------------------------------------------
static constexpr int ST_A  = 16384;
static constexpr int ST_SZ = 49152;

__device__ __forceinline__ void gemm_load_stage(
    uint32_t stage, const int8_t* Ag, const int8_t* Bg, int kt, int tid)
{
    const int k0 = kt << 7;
#pragma unroll
    for (int r = 0; r < 4; r++) {
        int c = tid + (r << 8);
        int row = c >> 3, seg = (c & 7) << 4;
        uint32_t dst = stage + row * 128 + (seg ^ ((row & 7) << 4));
        cp16(dst, Ag + (size_t)row * 16384 + k0 + seg);
    }
#pragma unroll
    for (int r = 0; r < 8; r++) {
        int c = tid + (r << 8);
        int row = c >> 3, seg = (c & 7) << 4;
        uint32_t dst = stage + ST_A + row * 128 + (seg ^ ((row & 7) << 4));
        cp16(dst, Bg + (size_t)row * 16384 + k0 + seg);
    }
}

__global__ __launch_bounds__(256, 1) void k_fc1imma()
{
    extern __shared__ char sm[];
    const uint32_t smb = smem_u32(sm);

    const int tid = threadIdx.x, wid = tid >> 5, l = tid & 31;
    const int warp_m = wid & 1, warp_n = wid >> 1;
    const int r = blockIdx.x;

    int u = (r * 8192) / 148;
    const int u1 = ((r + 1) * 8192) / 148;

    const int rowA = l & 15;
    const uint32_t cA = (uint32_t)(((l >> 4) << 4) ^ ((l & 7) << 4));
    const int rowB = (l & 7) + ((l >> 4) << 3);
    const uint32_t cB = (uint32_t)((((l >> 3) & 1) << 4) ^ ((l & 7) << 4));
    const uint32_t aBase = (uint32_t)((warp_m * 64 + rowA) * 128);
    const uint32_t bBase = (uint32_t)(ST_A + (warp_n * 64 + rowB) * 128);
    const int gm = l >> 2, gn = (l & 3) << 1;

    while (u < u1) {
        const int tile = u >> 7;
        const int kt0 = u & 127;
        const int its = min(128 - kt0, u1 - u);
        const int n0 = (tile & 7) * 256, m0 = (tile >> 3) * 128;
        const int8_t* Ag = g_a2  + (size_t)m0 * 16384;
        const int8_t* Bg = g_w1d + (size_t)n0 * 16384;

        int c[4][8][4];
#pragma unroll
        for (int i = 0; i < 4; i++)
#pragma unroll
            for (int nn = 0; nn < 8; nn++)
#pragma unroll
                for (int q = 0; q < 4; q++) c[i][nn][q] = 0;

        // prologue: up to 3 stages into buffers 0..2 (commit all 3 groups)
#pragma unroll
        for (int s = 0; s < 3; s++) {
            if (s < its)
                gemm_load_stage(smb + s * ST_SZ, Ag, Bg, kt0 + s, tid);
            asm volatile("cp.async.commit_group;" ::: "memory");
        }

        for (int v = 0; v < its; v++) {
            asm volatile("cp.async.wait_group 2;" ::: "memory");
            __syncthreads();
            if (v + 3 < its)
                gemm_load_stage(smb + ((v + 3) & 3) * ST_SZ, Ag, Bg,
                                kt0 + v + 3, tid);
            asm volatile("cp.async.commit_group;" ::: "memory");

            const uint32_t buf = smb + (v & 3) * ST_SZ;
#pragma unroll
            for (int kk = 0; kk < 4; kk++) {
                const uint32_t ka = ((uint32_t)(kk << 5)) ^ cA;
                const uint32_t kb = ((uint32_t)(kk << 5)) ^ cB;
                uint32_t a[4][4], b[4][4];
#pragma unroll
                for (int i = 0; i < 4; i++)
                    ldsm4(a[i], buf + aBase + i * 2048 + ka);
#pragma unroll
                for (int t = 0; t < 4; t++)
                    ldsm4(b[t], buf + bBase + t * 2048 + kb);
#pragma unroll
                for (int i = 0; i < 4; i++)
#pragma unroll
                    for (int t = 0; t < 4; t++) {
                        imma(c[i][2 * t],     a[i], b[t][0], b[t][1]);
                        imma(c[i][2 * t + 1], a[i], b[t][2], b[t][3]);
                    }
            }
        }
        asm volatile("cp.async.wait_all;" ::: "memory");
        __syncthreads();

        // epilogue: frags -> smem [128][260] -> atomicAdd partial (exact)
        int* so = (int*)sm;
#pragma unroll
        for (int i = 0; i < 4; i++) {
            int ml = warp_m * 64 + i * 16 + gm;
#pragma unroll
            for (int nn = 0; nn < 8; nn++) {
                int nl = warp_n * 64 + nn * 8 + gn;
                so[ml * 260 + nl]           = c[i][nn][0];
                so[ml * 260 + nl + 1]       = c[i][nn][1];
                so[(ml + 8) * 260 + nl]     = c[i][nn][2];
                so[(ml + 8) * 260 + nl + 1] = c[i][nn][3];
            }
        }
        __syncthreads();
        {
            int* gp = g_s32 + (size_t)m0 * 2048 + n0;
            for (int i = tid; i < 32768; i += 256) {
                int ml = i >> 8, nl = i & 255;
                atomicAdd(&gp[(size_t)ml * 2048 + nl], so[ml * 260 + nl]);
            }
        }
        __syncthreads();

        u += its;
    }
}

// ---------------------------------------------------------------------------
// Kernel 3b: tier-1.  V = S01*2^14 + B32 (int64).  |V| > R1_j -> sign.
// Else push to worklist.  One block per m.
// ---------------------------------------------------------------------------
__global__ __launch_bounds__(256) void k_recflag(const float* __restrict__ bf)
{
    __shared__ int s_cnt, s_base;
    __shared__ int s_list[1024];

    const int m = blockIdx.x, t = threadIdx.x;
    if (t == 0) s_cnt = 0;
    __syncthreads();

    const int* b0 = g_s32 + (size_t)m * 2048;
    const int4 h0 = ((const int4*)b0)[t];            // plane0
    const int4 h1 = ((const int4*)(b0 + 1024))[t];   // plane1
    const float4 bb = ((const float4*)bf)[t];
    const int4 Rr = ((const int4*)g_R1)[t];

    int sv[4] = {h0.x, h0.y, h0.z, h0.w};
    int lv[4] = {h1.x, h1.y, h1.z, h1.w};
    float bv[4] = {bb.x, bb.y, bb.z, bb.w};
    int Rv[4] = {Rr.x, Rr.y, Rr.z, Rr.w};

    char o[4] = {0, 0, 0, 0};
#pragma unroll
    for (int cix = 0; cix < 4; cix++) {
        long long S01 = ((long long)sv[cix] << 7) + lv[cix];
        long long B32 = __float2ll_rn(bv[cix] * 4294967296.0f);
        long long V = (S01 << 14) + B32;
        long long aV = (V < 0) ? -V : V;
        if (aV > (long long)Rv[cix]) {
            o[cix] = (char)((V > 0) ? 1 : -1);
        } else {
            int p = atomicAdd(&s_cnt, 1);
            s_list[p] = m * 1024 + t * 4 + cix;
        }
    }
    ((char4*)g_a3)[m * 256 + t] = make_char4(o[0], o[1], o[2], o[3]);
    __syncthreads();

    if (t == 0 && s_cnt > 0) s_base = atomicAdd(&g_cnt, s_cnt);
    __syncthreads();
    for (int i = t; i < s_cnt; i += 256) g_list[s_base + i] = s_list[i];
}

// ---------------------------------------------------------------------------
// Kernel 3c: tier-2.  One warp per entry; dp4a on planes 2,3 (exact).
// ---------------------------------------------------------------------------
__global__ __launch_bounds__(256) void k_fix2(const float* __restrict__ bf)
{
    const int tid = threadIdx.x, lane = tid & 31, w = tid >> 5;
    const int gw = blockIdx.x * 8 + w, stride = gridDim.x * 8;
    const int cnt = g_cnt;

    for (int e = gw; e < cnt; e += stride) {
        const int pair = g_list[e];
        const int m = pair >> 10, j = pair & 1023;
        const int* aw = (const int*)(g_a2 + (size_t)m * 16384);
        const int* p2 = (const int*)(g_w1d + 2ull * 16777216 + (size_t)j * 16384);
        const int* p3 = (const int*)(g_w1d + 3ull * 16777216 + (size_t)j * 16384);

        int s2 = 0, s3 = 0;
#pragma unroll 4
        for (int c = lane; c < 4096; c += 32) {
            int av = aw[c];
            s2 = __dp4a(p2[c], av, s2);
            s3 = __dp4a(p3[c], av, s3);
        }
#pragma unroll
        for (int off = 16; off; off >>= 1) {
            s2 += __shfl_xor_sync(0xffffffffu, s2, off);
            s3 += __shfl_xor_sync(0xffffffffu, s3, off);
        }
        if (lane == 0) {
            int S0 = g_s32[(size_t)m * 2048 + j];
            int S1 = g_s32[(size_t)m * 2048 + 1024 + j];
            long long S01 = ((long long)S0 << 7) + S1;
            long long B32 = __float2ll_rn(bf[j] * 4294967296.0f);
            long long T = (S01 << 14) + (long long)s2 * 128 + s3 + B32;
            long long aT = (T < 0) ? -T : T;
            if (aT > 8196) {
                g_a3[(size_t)m * 1024 + j] = (char)((T > 0) ? 1 : -1);
            } else {
                int p = atomicAdd(&g_cnt2, 1);
                g_list2[p] = pair;
            }
        }
    }
}

// ---------------------------------------------------------------------------
// Kernel 3d: tier-3.  fp64 dot with true fp32 weights (expected ~0-8 entries).
// ---------------------------------------------------------------------------
__global__ __launch_bounds__(256) void k_fix3(
    const float* __restrict__ W, const float* __restrict__ bf)
{
    __shared__ double rs[256];
    const int t = threadIdx.x;
    const int cnt = g_cnt2;

    for (int e = blockIdx.x; e < cnt; e += gridDim.x) {
        const int pair = g_list2[e];
        const int m = pair >> 10, j = pair & 1023;
        const float* wr = W + (size_t)j * 16384;
        const int8_t* ar = g_a2 + (size_t)m * 16384;

        double a0 = 0.0, a1 = 0.0, a2 = 0.0, a3 = 0.0;
        for (int k = t; k < 16384; k += 1024) {
            a0 += (double)wr[k]       * (double)ar[k];
            a1 += (double)wr[k + 256] * (double)ar[k + 256];
            a2 += (double)wr[k + 512] * (double)ar[k + 512];
            a3 += (double)wr[k + 768] * (double)ar[k + 768];
        }
        rs[t] = (a0 + a1) + (a2 + a3);
        __syncthreads();
        for (int s = 128; s; s >>= 1) {
            if (t < s) rs[t] += rs[t + s];
            __syncthreads();
        }
        if (t == 0) {
            double v = rs[0] + (double)bf[j];
            g_a3[(size_t)m * 1024 + j] =
                (char)((v > 0.0) ? 1 : ((v < 0.0) ? -1 : 0));
        }
        __syncthreads();
    }
}

// ---------------------------------------------------------------------------
// Kernel 4: fc2  out[1024][10] = a3 @ W2^T + b2
// ---------------------------------------------------------------------------
__global__ __launch_bounds__(128) void k_fc2(
    const float* __restrict__ W2, const float* __restrict__ b2,
    float* __restrict__ out)
{
    const int n = blockIdx.x, tid = threadIdx.x;
    float acc[10] = {};
    const int8_t* a = g_a3 + n * 1024;
    for (int k = tid; k < 1024; k += 128) {
        float s = (float)a[k];
#pragma unroll
        for (int j = 0; j < 10; j++) acc[j] += s * W2[j * 1024 + k];
    }
#pragma unroll
    for (int j = 0; j < 10; j++)
#pragma unroll
        for (int off = 16; off; off >>= 1)
            acc[j] += __shfl_down_sync(0xffffffffu, acc[j], off);

    __shared__ float red[4][10];
    int w = tid >> 5, lm = tid & 31;
    if (lm == 0)
#pragma unroll
        for (int j = 0; j < 10; j++) red[w][j] = acc[j];
    __syncthreads();
    if (tid < 10) {
        float v = red[0][tid] + red[1][tid] + red[2][tid] + red[3][tid] + b2[tid];
        out[n * 10 + tid] = v;
    }
}

// ---------------------------------------------------------------------------
extern "C" void kernel_launch(void* const* d_in, const int* in_sizes, int n_in,
                              void* d_out, int out_size)
{
    const float* x    = (const float*)d_in[0];
    const float* w1dw = (const float*)d_in[1];
    const float* b1dw = (const float*)d_in[2];
    const float* w1pw = (const float*)d_in[3];
    const float* b1pw = (const float*)d_in[4];
    const float* w2dw = (const float*)d_in[5];
    const float* b2dw = (const float*)d_in[6];
    const float* w2pw = (const float*)d_in[7];
    const float* b2pw = (const float*)d_in[8];
    const float* fc1w = (const float*)d_in[9];
    const float* fc1b = (const float*)d_in[10];
    const float* fc2w = (const float*)d_in[11];
    const float* fc2b = (const float*)d_in[12];
    float* out = (float*)d_out;

    cudaFuncSetAttribute(k_conv2, cudaFuncAttributeMaxDynamicSharedMemorySize, C2_SMEM);
    const int SMEMG = 4 * ST_SZ;   // 196608
    cudaFuncSetAttribute(k_fc1imma, cudaFuncAttributeMaxDynamicSharedMemorySize, SMEMG);

    k_zs<<<2048, 256>>>();
    k_wsplit<<<1024, 256>>>(fc1w);
    k_conv1<<<1024, 256>>>(x, w1dw, b1dw, w1pw, b1pw);
    k_conv2<<<1024, 256, C2_SMEM>>>(w2dw, b2dw, w2pw, b2pw);
    k_fc1imma<<<148, 256, SMEMG>>>();
    k_recflag<<<1024, 256>>>(fc1b);
    k_fix2<<<1024, 256>>>(fc1b);
    k_fix3<<<64, 256>>>(fc1w, fc1b);
    k_fc2<<<1024, 128>>>(fc2w, fc2b, out);
}

// round 17
// speedup vs baseline: 3.0763x; 1.0493x over previous
#include <cuda_runtime.h>
#include <cstdint>

// ---------------------------------------------------------------------------
// BinaryConnectNet forward (compute_103-safe: mma.sync/ldmatrix/cp.async).
//  conv1: dw3x3(g=3)+pw1x1(3->128), sign, maxpool2 -> a1 int8
//  conv2: dw dp4a (reg-hoisted selectors) + pw s8 IMMA (pool+sign fused)
//  fc1:   2-plane int8-digit IMMA GEMM, persistent 148-CTA grid, exact s32
//         atomicAdd; int tier-1 bound + dp4a tier-2 + tiny fp64 tier-3.
//  fc2:   a3 @ W2^T + b2 -> out [1024][10] fp32
// ---------------------------------------------------------------------------

__device__ int8_t g_a1[1024 * 256 * 128];
__device__ int8_t g_a2[1024 * 16384];
__device__ int8_t g_a3[1024 * 1024];
__device__ int8_t g_w1d[4ull * 1024 * 16384];   // [plane][j][k]
__device__ int    g_s32[1024ull * 2048];        // [m][n'] combined accumulator
__device__ int    g_R1[1024];                   // per-j tier1 bound (2^-32 units)
__device__ int    g_cnt,  g_cnt2;
__device__ int    g_list[1024 * 1024];
__device__ int    g_list2[1024 * 1024];

__device__ __forceinline__ float fsign(float v) {
    return (v > 0.f) ? 1.f : ((v < 0.f) ? -1.f : 0.f);
}
__device__ __forceinline__ int isign(int v) { return (v > 0) - (v < 0); }

__device__ __forceinline__ uint32_t smem_u32(const void* p) {
    uint32_t a;
    asm("{ .reg .u64 t; cvta.to.shared.u64 t, %1; cvt.u32.u64 %0, t; }"
        : "=r"(a) : "l"(p));
    return a;
}
__device__ __forceinline__ void cp16(uint32_t dst, const void* src) {
    asm volatile("cp.async.cg.shared.global [%0], [%1], 16;"
                 :: "r"(dst), "l"(src) : "memory");
}
__device__ __forceinline__ void ldsm4(uint32_t* r, uint32_t addr) {
    asm volatile("ldmatrix.sync.aligned.m8n8.x4.shared.b16 {%0,%1,%2,%3}, [%4];"
                 : "=r"(r[0]), "=r"(r[1]), "=r"(r[2]), "=r"(r[3]) : "r"(addr));
}
__device__ __forceinline__ void imma(int* c, const uint32_t* a,
                                     uint32_t b0, uint32_t b1) {
    asm volatile("mma.sync.aligned.m16n8k32.row.col.s32.s8.s8.s32 "
                 "{%0,%1,%2,%3}, {%4,%5,%6,%7}, {%8,%9}, {%0,%1,%2,%3};"
                 : "+r"(c[0]), "+r"(c[1]), "+r"(c[2]), "+r"(c[3])
                 : "r"(a[0]), "r"(a[1]), "r"(a[2]), "r"(a[3]),
                   "r"(b0), "r"(b1));
}

// ---------------------------------------------------------------------------
// Kernel Z: zero the s32 accumulator (8MB) + worklist counters.
// ---------------------------------------------------------------------------
__global__ __launch_bounds__(256) void k_zs()
{
    const size_t i = (size_t)blockIdx.x * 256 + threadIdx.x;
    ((int4*)g_s32)[i] = make_int4(0, 0, 0, 0);
    if (i == 0) { g_cnt = 0; g_cnt2 = 0; }
}

// ---------------------------------------------------------------------------
// Kernel 1: conv1 dw + pw + sign + maxpool, one image per block.
// ---------------------------------------------------------------------------
__global__ __launch_bounds__(256) void k_conv1(
    const float* __restrict__ x,
    const float* __restrict__ w1dw, const float* __restrict__ b1dw,
    const float* __restrict__ w1pw, const float* __restrict__ b1pw)
{
    __shared__ float sx[3][32][32];
    __shared__ float sdw[3][32][32];
    __shared__ float swdw[27];
    __shared__ float sbdw[3];
    __shared__ float swpw[128 * 3];
    __shared__ float sbpw[128];

    const int n = blockIdx.x, tid = threadIdx.x;

    for (int i = tid; i < 3072; i += 256) ((float*)sx)[i] = x[n * 3072 + i];
    if (tid < 27)  swdw[tid] = fsign(w1dw[tid]);
    if (tid < 3)   sbdw[tid] = fsign(b1dw[tid]);
    for (int i = tid; i < 384; i += 256) swpw[i] = fsign(w1pw[i]);
    if (tid < 128) sbpw[tid] = fsign(b1pw[tid]);
    __syncthreads();

    for (int i = tid; i < 3072; i += 256) {
        int c = i >> 10, p = i & 1023, y = p >> 5, xx = p & 31;
        float acc = 0.f;
#pragma unroll
        for (int ky = 0; ky < 3; ky++) {
#pragma unroll
            for (int kx = 0; kx < 3; kx++) {
                int yy = y + ky - 1, xw = xx + kx - 1;
                if (yy >= 0 && yy < 32 && xw >= 0 && xw < 32)
                    acc += swdw[c * 9 + ky * 3 + kx] * sx[c][yy][xw];
            }
        }
        acc += sbdw[c];
        ((float*)sdw)[i] = acc;
    }
    __syncthreads();

    for (int i = tid; i < 32768; i += 256) {
        int oc = i & 127, pp = i >> 7;
        int oy = pp >> 4, ox = pp & 15;
        float w0 = swpw[oc * 3 + 0], w1 = swpw[oc * 3 + 1],
              w2 = swpw[oc * 3 + 2], bb = sbpw[oc];
        float vmax = -1e30f;
#pragma unroll
        for (int d = 0; d < 4; d++) {
            int y = 2 * oy + (d >> 1), xw = 2 * ox + (d & 1);
            float v = w0 * sdw[0][y][xw] + w1 * sdw[1][y][xw]
                    + w2 * sdw[2][y][xw] + bb;
            vmax = fmaxf(vmax, v);
        }
        g_a1[n * 32768 + pp * 128 + oc] = (int8_t)(int)fsign(vmax);
    }
}

// ---------------------------------------------------------------------------
// Kernel 2: conv2.  dw via masked dp4a with register-hoisted selectors;
// pw via s8 mma.sync with pool+sign fused.  One image per block, 2/SM.
// ---------------------------------------------------------------------------
static constexpr int C2_SMEM = 103424;

__global__ void __launch_bounds__(256, 2) k_conv2(
    const float* __restrict__ w2dw, const float* __restrict__ b2dw,
    const float* __restrict__ w2pw, const float* __restrict__ b2pw)
{
    extern __shared__ char sm[];
    int8_t*   s_a1 = (int8_t*)sm;
    int8_t*   s_t  = (int8_t*)(sm + 32768);
    int8_t*   s_w  = (int8_t*)(sm + 65536);
    uint32_t* s_pk = (uint32_t*)(sm + 98304);
    int8_t*   s_bd = (int8_t*)(sm + 102912);
    int8_t*   s_bp = (int8_t*)(sm + 103040);

    const int n = blockIdx.x, tid = threadIdx.x;

    {
        const uint4* src = (const uint4*)(g_a1 + n * 32768);
        uint4* dst = (uint4*)s_a1;
        for (int i = tid; i < 2048; i += 256) dst[i] = src[i];
    }
    for (int i = tid; i < 1152; i += 256) {
        int c4 = i / 36, rem = i % 36, tap = rem >> 2, ch = rem & 3;
        int s = (int)fsign(w2dw[(c4 * 4 + ch) * 9 + tap]);
        s_pk[(c4 * 9 + tap) * 4 + ch] = ((uint32_t)(uint8_t)(char)s) << (8 * ch);
    }
    // pw weights: float4 load -> char4 swizzled store (4B contiguity holds
    // under the XOR-16B swizzle since cc&15 spans one segment)
    for (int i = tid; i < 8192; i += 256) {
        int oc = i >> 5, g4 = i & 31;
        float4 wv = ((const float4*)w2pw)[i];
        int cc = g4 * 4;
        uint32_t sw = oc * 128 + ((((cc >> 4) ^ (oc & 7)) << 4) | (cc & 15));
        *(char4*)(s_w + sw) = make_char4(
            (char)(int)fsign(wv.x), (char)(int)fsign(wv.y),
            (char)(int)fsign(wv.z), (char)(int)fsign(wv.w));
    }
    if (tid < 128) s_bd[tid] = (int8_t)(int)fsign(b2dw[tid]);
    s_bp[tid] = (int8_t)(int)fsign(b2pw[tid]);
    __syncthreads();

    // depthwise 3x3 pad=1: c4 = tid&31 is loop-invariant -> hoist the 36
    // selector words and 4 biases into registers once per thread.
    {
        const int c4 = tid & 31;
        uint32_t pkr[36];
#pragma unroll
        for (int q = 0; q < 36; q++) pkr[q] = s_pk[c4 * 36 + q];
        const int bb0 = (int)s_bd[c4 * 4 + 0], bb1 = (int)s_bd[c4 * 4 + 1];
        const int bb2 = (int)s_bd[c4 * 4 + 2], bb3 = (int)s_bd[c4 * 4 + 3];
        const int pbase = tid >> 5;

#pragma unroll 4
        for (int it = 0; it < 32; it++) {
            const int p = pbase + (it << 3);
            const int y = p >> 4, xx = p & 15;
            int a0 = bb0, a1 = bb1, a2 = bb2, a3 = bb3;
#pragma unroll
            for (int ky = 0; ky < 3; ky++) {
#pragma unroll
                for (int kx = 0; kx < 3; kx++) {
                    int yy = y + ky - 1, xw = xx + kx - 1;
                    if (yy >= 0 && yy < 16 && xw >= 0 && xw < 16) {
                        int A = *(const int*)(s_a1 + (yy * 16 + xw) * 128 + c4 * 4);
                        const int tap = ky * 3 + kx;
                        a0 = __dp4a(A, (int)pkr[tap * 4 + 0], a0);
                        a1 = __dp4a(A, (int)pkr[tap * 4 + 1], a1);
                        a2 = __dp4a(A, (int)pkr[tap * 4 + 2], a2);
                        a3 = __dp4a(A, (int)pkr[tap * 4 + 3], a3);
                    }
                }
            }
            int cc = c4 * 4;
            uint32_t sw = p * 128 + ((((cc >> 4) ^ (p & 7)) << 4) | (cc & 15));
            *(char4*)(s_t + sw) =
                make_char4((char)a0, (char)a1, (char)a2, (char)a3);
        }
    }
    __syncthreads();

    // pointwise 128->256 via mma.sync; pool+bias+sign fused in epilogue.
    {
        const uint32_t smb = smem_u32(sm);
        const uint32_t tB = smb + 32768, wBs = smb + 65536;
        const int wid = tid >> 5, l = tid & 31;
        const int rowA = l & 15;
        const uint32_t cA = (uint32_t)(((l >> 4) << 4) ^ ((l & 7) << 4));
        const int rowB = (l & 7) + ((l >> 4) << 3);
        const uint32_t cB = (uint32_t)((((l >> 3) & 1) << 4) ^ ((l & 7) << 4));
        const uint32_t aBase = tB + (wid * 32 + rowA) * 128;
        const int gm = l >> 2, gn2 = (l & 3) << 1;
        int8_t* s_out = s_a1;

        for (int r = 0; r < 4; r++) {
            const uint32_t bBase = wBs + (r * 64 + rowB) * 128;
            int c[2][8][4];
#pragma unroll
            for (int i = 0; i < 2; i++)
#pragma unroll
                for (int nn = 0; nn < 8; nn++)
#pragma unroll
                    for (int q = 0; q < 4; q++) c[i][nn][q] = 0;

#pragma unroll
            for (int kk = 0; kk < 4; kk++) {
                const uint32_t ka = ((uint32_t)(kk << 5)) ^ cA;
                const uint32_t kb = ((uint32_t)(kk << 5)) ^ cB;
                uint32_t a[2][4], b[4][4];
                ldsm4(a[0], aBase + 0 * 2048 + ka);
                ldsm4(a[1], aBase + 1 * 2048 + ka);
#pragma unroll
                for (int t = 0; t < 4; t++)
                    ldsm4(b[t], bBase + t * 2048 + kb);
#pragma unroll
                for (int i = 0; i < 2; i++)
#pragma unroll
                    for (int t = 0; t < 4; t++) {
                        imma(c[i][2 * t],     a[i], b[t][0], b[t][1]);
                        imma(c[i][2 * t + 1], a[i], b[t][2], b[t][3]);
                    }
            }

#pragma unroll
            for (int nn = 0; nn < 8; nn++) {
                int m0 = max(c[0][nn][0], c[1][nn][0]);
                int m1 = max(c[0][nn][1], c[1][nn][1]);
                int m2 = max(c[0][nn][2], c[1][nn][2]);
                int m3 = max(c[0][nn][3], c[1][nn][3]);
                m0 = max(m0, __shfl_xor_sync(0xffffffffu, m0, 4));
                m1 = max(m1, __shfl_xor_sync(0xffffffffu, m1, 4));
                m2 = max(m2, __shfl_xor_sync(0xffffffffu, m2, 4));
                m3 = max(m3, __shfl_xor_sync(0xffffffffu, m3, 4));
                if ((l & 4) == 0) {
                    int oc0 = r * 64 + nn * 8 + gn2;
                    int b0 = (int)s_bp[oc0], b1 = (int)s_bp[oc0 + 1];
                    int qx = gm >> 1;
                    s_out[oc0 * 64 + wid * 8 + qx]           = (int8_t)isign(m0 + b0);
                    s_out[(oc0 + 1) * 64 + wid * 8 + qx]     = (int8_t)isign(m1 + b1);
                    s_out[oc0 * 64 + wid * 8 + qx + 4]       = (int8_t)isign(m2 + b0);
                    s_out[(oc0 + 1) * 64 + wid * 8 + qx + 4] = (int8_t)isign(m3 + b1);
                }
            }
        }
    }
    __syncthreads();

    {
        uint4* g = (uint4*)(g_a2 + n * 16384);
        const uint4* s2 = (const uint4*)s_a1;
        for (int i = tid; i < 1024; i += 256) g[i] = s2[i];
    }
}

// ---------------------------------------------------------------------------
// Kernel W: 4 digit planes + int residual bound (no fp64).
// ---------------------------------------------------------------------------
__global__ __launch_bounds__(256) void k_wsplit(const float* __restrict__ W)
{
    __shared__ int rs[256];
    const int j = blockIdx.x, tid = threadIdx.x;
    const float4* W4 = (const float4*)(W + (size_t)j * 16384);
    char4* P0 = (char4*)(g_w1d + 0ull * 16777216 + (size_t)j * 16384);
    char4* P1 = (char4*)(g_w1d + 1ull * 16777216 + (size_t)j * 16384);
    char4* P2 = (char4*)(g_w1d + 2ull * 16777216 + (size_t)j * 16384);
    char4* P3 = (char4*)(g_w1d + 3ull * 16777216 + (size_t)j * 16384);

    int racc = 0;
#pragma unroll 4
    for (int it = 0; it < 16; it++) {
        const int k4 = tid + (it << 8);
        float4 w = W4[k4];
        float wv[4] = {w.x, w.y, w.z, w.w};
        char dd0[4], dd1[4], dd2[4], dd3[4];
#pragma unroll
        for (int c = 0; c < 4; c++) {
            int n18 = __float2int_rn(wv[c] * 262144.0f);
            n18 = max(-16256, min(16256, n18));
            int d0 = (n18 + 64) >> 7;
            int d1 = n18 - (d0 << 7);
            int w32 = __float2int_rn(wv[c] * 4294967296.0f);
            int r32 = w32 - (n18 << 14);
            int d2 = (r32 + 64) >> 7;
            d2 = max(-127, min(127, d2));
            int d3 = r32 - (d2 << 7);
            d3 = max(-127, min(127, d3));
            racc += abs(r32);
            dd0[c] = (char)d0; dd1[c] = (char)d1;
            dd2[c] = (char)d2; dd3[c] = (char)d3;
        }
        P0[k4] = make_char4(dd0[0], dd0[1], dd0[2], dd0[3]);
        P1[k4] = make_char4(dd1[0], dd1[1], dd1[2], dd1[3]);
        P2[k4] = make_char4(dd2[0], dd2[1], dd2[2], dd2[3]);
        P3[k4] = make_char4(dd3[0], dd3[1], dd3[2], dd3[3]);
    }
    rs[tid] = racc;
    __syncthreads();
    for (int s = 128; s; s >>= 1) {
        if (tid < s) rs[tid] += rs[tid + s];
        __syncthreads();
    }
    if (tid == 0) g_R1[j] = rs[0] + 8192 + 4;
}

// ---------------------------------------------------------------------------
// Kernel 3: fc1 IMMA GEMM, PERSISTENT.  Grid = 148 CTAs.
// Work = 64 spatial tiles (8m x 8n of 128x256) x 128 K-its = 8192 units.
// ---------------------------------------------------------------------------
static constexpr int ST_A  = 16384;
static constexpr int ST_SZ = 49152;

__device__ __forceinline__ void gemm_load_stage(
    uint32_t stage, const int8_t* Ag, const int8_t* Bg, int kt, int tid)
{
    const int k0 = kt << 7;
#pragma unroll
    for (int r = 0; r < 4; r++) {
        int c = tid + (r << 8);
        int row = c >> 3, seg = (c & 7) << 4;
        uint32_t dst = stage + row * 128 + (seg ^ ((row & 7) << 4));
        cp16(dst, Ag + (size_t)row * 16384 + k0 + seg);
    }
#pragma unroll
    for (int r = 0; r < 8; r++) {
        int c = tid + (r << 8);
        int row = c >> 3, seg = (c & 7) << 4;
        uint32_t dst = stage + ST_A + row * 128 + (seg ^ ((row & 7) << 4));
        cp16(dst, Bg + (size_t)row * 16384 + k0 + seg);
    }
}

__global__ __launch_bounds__(256, 1) void k_fc1imma()
{
    extern __shared__ char sm[];
    const uint32_t smb = smem_u32(sm);

    const int tid = threadIdx.x, wid = tid >> 5, l = tid & 31;
    const int warp_m = wid & 1, warp_n = wid >> 1;
    const int r = blockIdx.x;

    int u = (r * 8192) / 148;
    const int u1 = ((r + 1) * 8192) / 148;

    const int rowA = l & 15;
    const uint32_t cA = (uint32_t)(((l >> 4) << 4) ^ ((l & 7) << 4));
    const int rowB = (l & 7) + ((l >> 4) << 3);
    const uint32_t cB = (uint32_t)((((l >> 3) & 1) << 4) ^ ((l & 7) << 4));
    const uint32_t aBase = (uint32_t)((warp_m * 64 + rowA) * 128);
    const uint32_t bBase = (uint32_t)(ST_A + (warp_n * 64 + rowB) * 128);
    const int gm = l >> 2, gn = (l & 3) << 1;

    while (u < u1) {
        const int tile = u >> 7;
        const int kt0 = u & 127;
        const int its = min(128 - kt0, u1 - u);
        const int n0 = (tile & 7) * 256, m0 = (tile >> 3) * 128;
        const int8_t* Ag = g_a2  + (size_t)m0 * 16384;
        const int8_t* Bg = g_w1d + (size_t)n0 * 16384;

        int c[4][8][4];
#pragma unroll
        for (int i = 0; i < 4; i++)
#pragma unroll
            for (int nn = 0; nn < 8; nn++)
#pragma unroll
                for (int q = 0; q < 4; q++) c[i][nn][q] = 0;

#pragma unroll
        for (int s = 0; s < 3; s++) {
            if (s < its)
                gemm_load_stage(smb + s * ST_SZ, Ag, Bg, kt0 + s, tid);
            asm volatile("cp.async.commit_group;" ::: "memory");
        }

        for (int v = 0; v < its; v++) {
            asm volatile("cp.async.wait_group 2;" ::: "memory");
            __syncthreads();
            if (v + 3 < its)
                gemm_load_stage(smb + ((v + 3) & 3) * ST_SZ, Ag, Bg,
                                kt0 + v + 3, tid);
            asm volatile("cp.async.commit_group;" ::: "memory");

            const uint32_t buf = smb + (v & 3) * ST_SZ;
#pragma unroll
            for (int kk = 0; kk < 4; kk++) {
                const uint32_t ka = ((uint32_t)(kk << 5)) ^ cA;
                const uint32_t kb = ((uint32_t)(kk << 5)) ^ cB;
                uint32_t a[4][4], b[4][4];
#pragma unroll
                for (int i = 0; i < 4; i++)
                    ldsm4(a[i], buf + aBase + i * 2048 + ka);
#pragma unroll
                for (int t = 0; t < 4; t++)
                    ldsm4(b[t], buf + bBase + t * 2048 + kb);
#pragma unroll
                for (int i = 0; i < 4; i++)
#pragma unroll
                    for (int t = 0; t < 4; t++) {
                        imma(c[i][2 * t],     a[i], b[t][0], b[t][1]);
                        imma(c[i][2 * t + 1], a[i], b[t][2], b[t][3]);
                    }
            }
        }
        asm volatile("cp.async.wait_all;" ::: "memory");
        __syncthreads();

        int* so = (int*)sm;
#pragma unroll
        for (int i = 0; i < 4; i++) {
            int ml = warp_m * 64 + i * 16 + gm;
#pragma unroll
            for (int nn = 0; nn < 8; nn++) {
                int nl = warp_n * 64 + nn * 8 + gn;
                so[ml * 260 + nl]           = c[i][nn][0];
                so[ml * 260 + nl + 1]       = c[i][nn][1];
                so[(ml + 8) * 260 + nl]     = c[i][nn][2];
                so[(ml + 8) * 260 + nl + 1] = c[i][nn][3];
            }
        }
        __syncthreads();
        {
            int* gp = g_s32 + (size_t)m0 * 2048 + n0;
            for (int i = tid; i < 32768; i += 256) {
                int ml = i >> 8, nl = i & 255;
                atomicAdd(&gp[(size_t)ml * 2048 + nl], so[ml * 260 + nl]);
            }
        }
        __syncthreads();

        u += its;
    }
}

// ---------------------------------------------------------------------------
// Kernel 3b: tier-1.  V = S01*2^14 + B32 (int64).  |V| > R1_j -> sign.
// ---------------------------------------------------------------------------
__global__ __launch_bounds__(256) void k_recflag(const float* __restrict__ bf)
{
    __shared__ int s_cnt, s_base;
    __shared__ int s_list[1024];

    const int m = blockIdx.x, t = threadIdx.x;
    if (t == 0) s_cnt = 0;
    __syncthreads();

    const int* b0 = g_s32 + (size_t)m * 2048;
    const int4 h0 = ((const int4*)b0)[t];
    const int4 h1 = ((const int4*)(b0 + 1024))[t];
    const float4 bb = ((const float4*)bf)[t];
    const int4 Rr = ((const int4*)g_R1)[t];

    int sv[4] = {h0.x, h0.y, h0.z, h0.w};
    int lv[4] = {h1.x, h1.y, h1.z, h1.w};
    float bv[4] = {bb.x, bb.y, bb.z, bb.w};
    int Rv[4] = {Rr.x, Rr.y, Rr.z, Rr.w};

    char o[4] = {0, 0, 0, 0};
#pragma unroll
    for (int cix = 0; cix < 4; cix++) {
        long long S01 = ((long long)sv[cix] << 7) + lv[cix];
        long long B32 = __float2ll_rn(bv[cix] * 4294967296.0f);
        long long V = (S01 << 14) + B32;
        long long aV = (V < 0) ? -V : V;
        if (aV > (long long)Rv[cix]) {
            o[cix] = (char)((V > 0) ? 1 : -1);
        } else {
            int p = atomicAdd(&s_cnt, 1);
            s_list[p] = m * 1024 + t * 4 + cix;
        }
    }
    ((char4*)g_a3)[m * 256 + t] = make_char4(o[0], o[1], o[2], o[3]);
    __syncthreads();

    if (t == 0 && s_cnt > 0) s_base = atomicAdd(&g_cnt, s_cnt);
    __syncthreads();
    for (int i = t; i < s_cnt; i += 256) g_list[s_base + i] = s_list[i];
}

// ---------------------------------------------------------------------------
// Kernel 3c: tier-2.  One warp per entry; dp4a on planes 2,3 (exact).
// ---------------------------------------------------------------------------
__global__ __launch_bounds__(256) void k_fix2(const float* __restrict__ bf)
{
    const int tid = threadIdx.x, lane = tid & 31, w = tid >> 5;
    const int gw = blockIdx.x * 8 + w, stride = gridDim.x * 8;
    const int cnt = g_cnt;

    for (int e = gw; e < cnt; e += stride) {
        const int pair = g_list[e];
        const int m = pair >> 10, j = pair & 1023;
        const int* aw = (const int*)(g_a2 + (size_t)m * 16384);
        const int* p2 = (const int*)(g_w1d + 2ull * 16777216 + (size_t)j * 16384);
        const int* p3 = (const int*)(g_w1d + 3ull * 16777216 + (size_t)j * 16384);

        int s2 = 0, s3 = 0;
#pragma unroll 4
        for (int c = lane; c < 4096; c += 32) {
            int av = aw[c];
            s2 = __dp4a(p2[c], av, s2);
            s3 = __dp4a(p3[c], av, s3);
        }
#pragma unroll
        for (int off = 16; off; off >>= 1) {
            s2 += __shfl_xor_sync(0xffffffffu, s2, off);
            s3 += __shfl_xor_sync(0xffffffffu, s3, off);
        }
        if (lane == 0) {
            int S0 = g_s32[(size_t)m * 2048 + j];
            int S1 = g_s32[(size_t)m * 2048 + 1024 + j];
            long long S01 = ((long long)S0 << 7) + S1;
            long long B32 = __float2ll_rn(bf[j] * 4294967296.0f);
            long long T = (S01 << 14) + (long long)s2 * 128 + s3 + B32;
            long long aT = (T < 0) ? -T : T;
            if (aT > 8196) {
                g_a3[(size_t)m * 1024 + j] = (char)((T > 0) ? 1 : -1);
            } else {
                int p = atomicAdd(&g_cnt2, 1);
                g_list2[p] = pair;
            }
        }
    }
}

// ---------------------------------------------------------------------------
// Kernel 3d: tier-3.  fp64 dot with true fp32 weights (expected ~0-8 entries).
// ---------------------------------------------------------------------------
__global__ __launch_bounds__(256) void k_fix3(
    const float* __restrict__ W, const float* __restrict__ bf)
{
    __shared__ double rs[256];
    const int t = threadIdx.x;
    const int cnt = g_cnt2;

    for (int e = blockIdx.x; e < cnt; e += gridDim.x) {
        const int pair = g_list2[e];
        const int m = pair >> 10, j = pair & 1023;
        const float* wr = W + (size_t)j * 16384;
        const int8_t* ar = g_a2 + (size_t)m * 16384;

        double a0 = 0.0, a1 = 0.0, a2 = 0.0, a3 = 0.0;
        for (int k = t; k < 16384; k += 1024) {
            a0 += (double)wr[k]       * (double)ar[k];
            a1 += (double)wr[k + 256] * (double)ar[k + 256];
            a2 += (double)wr[k + 512] * (double)ar[k + 512];
            a3 += (double)wr[k + 768] * (double)ar[k + 768];
        }
        rs[t] = (a0 + a1) + (a2 + a3);
        __syncthreads();
        for (int s = 128; s; s >>= 1) {
            if (t < s) rs[t] += rs[t + s];
            __syncthreads();
        }
        if (t == 0) {
            double v = rs[0] + (double)bf[j];
            g_a3[(size_t)m * 1024 + j] =
                (char)((v > 0.0) ? 1 : ((v < 0.0) ? -1 : 0));
        }
        __syncthreads();
    }
}

// ---------------------------------------------------------------------------
// Kernel 4: fc2  out[1024][10] = a3 @ W2^T + b2
// ---------------------------------------------------------------------------
__global__ __launch_bounds__(128) void k_fc2(
    const float* __restrict__ W2, const float* __restrict__ b2,
    float* __restrict__ out)
{
    const int n = blockIdx.x, tid = threadIdx.x;
    float acc[10] = {};
    const int8_t* a = g_a3 + n * 1024;
    for (int k = tid; k < 1024; k += 128) {
        float s = (float)a[k];
#pragma unroll
        for (int j = 0; j < 10; j++) acc[j] += s * W2[j * 1024 + k];
    }
#pragma unroll
    for (int j = 0; j < 10; j++)
#pragma unroll
        for (int off = 16; off; off >>= 1)
            acc[j] += __shfl_down_sync(0xffffffffu, acc[j], off);

    __shared__ float red[4][10];
    int w = tid >> 5, lm = tid & 31;
    if (lm == 0)
#pragma unroll
        for (int j = 0; j < 10; j++) red[w][j] = acc[j];
    __syncthreads();
    if (tid < 10) {
        float v = red[0][tid] + red[1][tid] + red[2][tid] + red[3][tid] + b2[tid];
        out[n * 10 + tid] = v;
    }
}

// ---------------------------------------------------------------------------
extern "C" void kernel_launch(void* const* d_in, const int* in_sizes, int n_in,
                              void* d_out, int out_size)
{
    const float* x    = (const float*)d_in[0];
    const float* w1dw = (const float*)d_in[1];
    const float* b1dw = (const float*)d_in[2];
    const float* w1pw = (const float*)d_in[3];
    const float* b1pw = (const float*)d_in[4];
    const float* w2dw = (const float*)d_in[5];
    const float* b2dw = (const float*)d_in[6];
    const float* w2pw = (const float*)d_in[7];
    const float* b2pw = (const float*)d_in[8];
    const float* fc1w = (const float*)d_in[9];
    const float* fc1b = (const float*)d_in[10];
    const float* fc2w = (const float*)d_in[11];
    const float* fc2b = (const float*)d_in[12];
    float* out = (float*)d_out;

    cudaFuncSetAttribute(k_conv2, cudaFuncAttributeMaxDynamicSharedMemorySize, C2_SMEM);
    const int SMEMG = 4 * ST_SZ;   // 196608
    cudaFuncSetAttribute(k_fc1imma, cudaFuncAttributeMaxDynamicSharedMemorySize, SMEMG);

    k_zs<<<2048, 256>>>();
    k_wsplit<<<1024, 256>>>(fc1w);
    k_conv1<<<1024, 256>>>(x, w1dw, b1dw, w1pw, b1pw);
    k_conv2<<<1024, 256, C2_SMEM>>>(w2dw, b2dw, w2pw, b2pw);
    k_fc1imma<<<148, 256, SMEMG>>>();
    k_recflag<<<1024, 256>>>(fc1b);
    k_fix2<<<1024, 256>>>(fc1b);
    k_fix3<<<64, 256>>>(fc1w, fc1b);
    k_fc2<<<1024, 128>>>(fc2w, fc2b, out);
}